// round 1
// baseline (speedup 1.0000x reference)
#include <cuda_runtime.h>
#include <cuda_bf16.h>

// Problem constants (fixed by the reference)
#define NN 50000
#define EE 500000
#define FF 64
#define HH 2
#define GG 128

// ---------------- scratch (static __device__ globals; no runtime alloc) ----------------
__device__ float d_h1[NN * 128];     // layer1 linear out
__device__ float d_agg1[NN * 128];   // layer1 aggregate -> y1 (in place)
__device__ float d_x2[NN * 128];     // layer1 post-BN+relu (layer2 input)
__device__ float d_h2[NN * 256];     // layer2 linear out
__device__ float d_agg2[NN * 256];
__device__ float d_x3[NN * 256];     // layer2 post-BN+relu
__device__ float d_es1[NN * 2], d_ed1[NN * 2], d_den1[NN * 2];
__device__ unsigned d_menc1[NN * 2];
__device__ float d_es2[NN * 2], d_ed2[NN * 2], d_den2[NN * 2];
__device__ unsigned d_menc2[NN * 2];
__device__ float d_bnsum[256], d_bnsq[256], d_mu[256], d_rstd[256];
__device__ float d_pooled[GG * 256], d_counts[GG];
__device__ float d_z1[GG * 512], d_z1n[GG * 512];
__device__ float d_z2[GG * 256], d_z2n[GG * 256];

// ---------------- helpers ----------------
__device__ __forceinline__ unsigned enc_f(float f) {
    unsigned u = __float_as_uint(f);
    return (u & 0x80000000u) ? ~u : (u | 0x80000000u);
}
__device__ __forceinline__ float dec_f(unsigned k) {
    return (k & 0x80000000u) ? __uint_as_float(k ^ 0x80000000u) : __uint_as_float(~k);
}

__global__ void fillf(float* p, long n, float v) {
    long i = (long)blockIdx.x * blockDim.x + threadIdx.x;
    if (i < n) p[i] = v;
}

// ---------------- tiled fp32 GEMM: C[M,N] = A[M,K] @ B[K,N] ----------------
// BM=64, BN=64, BK=16, TM=TN=4, 256 threads. Requires N%64==0, K%16==0 (true here).
__global__ void gemm_kernel(const float* __restrict__ A, const float* __restrict__ B,
                            float* __restrict__ C, int M, int N, int K) {
    __shared__ float As[16][64];
    __shared__ float Bs[16][64];
    const int block_row = blockIdx.y * 64;
    const int block_col = blockIdx.x * 64;
    const int tid = threadIdx.x;
    const int tr = tid / 16, tc = tid % 16;
    float acc[4][4] = {};
    for (int k0 = 0; k0 < K; k0 += 16) {
        #pragma unroll
        for (int i = tid; i < 64 * 16; i += 256) {
            int r = i / 16, c = i % 16;
            int gr = block_row + r;
            As[c][r] = (gr < M) ? A[(long)gr * K + k0 + c] : 0.f;
        }
        #pragma unroll
        for (int i = tid; i < 16 * 64; i += 256) {
            int r = i / 64, c = i % 64;
            Bs[r][c] = B[(long)(k0 + r) * N + block_col + c];
        }
        __syncthreads();
        #pragma unroll
        for (int kk = 0; kk < 16; kk++) {
            float a[4], b[4];
            #pragma unroll
            for (int i = 0; i < 4; i++) a[i] = As[kk][tr * 4 + i];
            #pragma unroll
            for (int j = 0; j < 4; j++) b[j] = Bs[kk][tc * 4 + j];
            #pragma unroll
            for (int i = 0; i < 4; i++)
                #pragma unroll
                for (int j = 0; j < 4; j++) acc[i][j] += a[i] * b[j];
        }
        __syncthreads();
    }
    #pragma unroll
    for (int i = 0; i < 4; i++) {
        int gr = block_row + tr * 4 + i;
        if (gr < M) {
            #pragma unroll
            for (int j = 0; j < 4; j++)
                C[(long)gr * N + block_col + tc * 4 + j] = acc[i][j];
        }
    }
}

// ---------------- per-node attention coefficients ----------------
__global__ void attn_coef(const float* __restrict__ h, const float* __restrict__ a_s,
                          const float* __restrict__ a_d, float* __restrict__ es,
                          float* __restrict__ ed, int n_nodes, int D) {
    int idx = blockIdx.x * blockDim.x + threadIdx.x;
    if (idx >= n_nodes * HH) return;
    int n = idx / HH, hh = idx % HH;
    const float* hp = h + (long)n * HH * D + hh * D;
    const float* as = a_s + hh * D;
    const float* ad = a_d + hh * D;
    float s1 = 0.f, s2 = 0.f;
    for (int d = 0; d < D; d++) { float v = hp[d]; s1 += v * as[d]; s2 += v * ad[d]; }
    es[idx] = s1;
    ed[idx] = s2;
}

// ---------------- edge pass A: segment max (float-encoded atomicMax) ----------------
__global__ void edge_max(const int* __restrict__ src, const int* __restrict__ dst,
                         const float* __restrict__ es, const float* __restrict__ ed,
                         unsigned* __restrict__ menc) {
    int e = blockIdx.x * blockDim.x + threadIdx.x;
    if (e >= EE + NN) return;
    int s, t;
    if (e < EE) { s = src[e]; t = dst[e]; } else { s = t = e - EE; }
    #pragma unroll
    for (int hh = 0; hh < HH; hh++) {
        float v = es[s * 2 + hh] + ed[t * 2 + hh];
        v = v > 0.f ? v : 0.2f * v;
        atomicMax(&menc[t * 2 + hh], enc_f(v));
    }
}

// ---------------- edge pass B: softmax weight + weighted scatter ----------------
template <int C, int D>
__global__ void edge_scatter(const int* __restrict__ src, const int* __restrict__ dst,
                             const float* __restrict__ es, const float* __restrict__ ed,
                             const unsigned* __restrict__ menc, const float* __restrict__ h,
                             float* __restrict__ agg, float* __restrict__ den) {
    int gtid = blockIdx.x * blockDim.x + threadIdx.x;
    int e = gtid >> 5, lane = gtid & 31;
    if (e >= EE + NN) return;
    int s, t;
    if (e < EE) { s = src[e]; t = dst[e]; } else { s = t = e - EE; }
    float w[2];
    #pragma unroll
    for (int hh = 0; hh < HH; hh++) {
        float v = es[s * 2 + hh] + ed[t * 2 + hh];
        v = v > 0.f ? v : 0.2f * v;
        w[hh] = __expf(v - dec_f(menc[t * 2 + hh]));
    }
    if (lane == 0) {
        atomicAdd(&den[t * 2 + 0], w[0]);
        atomicAdd(&den[t * 2 + 1], w[1]);
    }
    const float* hp = h + (long)s * C;
    float* ap = agg + (long)t * C;
    #pragma unroll
    for (int i = 0; i < C / 128; i++) {
        int c = i * 128 + lane * 4;
        float4 hv = *(const float4*)(hp + c);
        float ww = (c < D) ? w[0] : w[1];
        atomicAdd(ap + c + 0, hv.x * ww);
        atomicAdd(ap + c + 1, hv.y * ww);
        atomicAdd(ap + c + 2, hv.z * ww);
        atomicAdd(ap + c + 3, hv.w * ww);
    }
}

// ---------------- finalize: agg / denom + bias ----------------
__global__ void gat_finalize(float* __restrict__ agg, const float* __restrict__ den,
                             const float* __restrict__ bias, int C, int D) {
    long idx = (long)blockIdx.x * blockDim.x + threadIdx.x;
    if (idx >= (long)NN * C) return;
    int n = idx / C, c = idx % C;
    agg[idx] = agg[idx] / (den[n * 2 + (c >= D ? 1 : 0)] + 1e-16f) + bias[c];
}

// ---------------- batchnorm over N rows ----------------
__global__ void bn_stats_part(const float* __restrict__ x, float* __restrict__ gsum,
                              float* __restrict__ gsq, int rows, int C) {
    int c = threadIdx.x;  // blockDim.x == C
    float s = 0.f, sq = 0.f;
    for (int r = blockIdx.x; r < rows; r += gridDim.x) {
        float v = x[(long)r * C + c];
        s += v; sq += v * v;
    }
    atomicAdd(&gsum[c], s);
    atomicAdd(&gsq[c], sq);
}

__global__ void bn_finalize(const float* __restrict__ gsum, const float* __restrict__ gsq,
                            float* __restrict__ mu, float* __restrict__ rstd, int rows, int C) {
    int c = blockIdx.x * blockDim.x + threadIdx.x;
    if (c >= C) return;
    float m = gsum[c] / (float)rows;
    float var = gsq[c] / (float)rows - m * m;
    mu[c] = m;
    rstd[c] = rsqrtf(var + 1e-5f);
}

__global__ void bn_apply_relu(const float* __restrict__ in, const float* __restrict__ mu,
                              const float* __restrict__ rstd, const float* __restrict__ g,
                              const float* __restrict__ b, float* __restrict__ out,
                              long total, int C) {
    long i = (long)blockIdx.x * blockDim.x + threadIdx.x;
    if (i >= total) return;
    int c = i % C;
    float v = (in[i] - mu[c]) * rstd[c] * g[c] + b[c];
    out[i] = fmaxf(v, 0.f);
}

// ---------------- pooling ----------------
__global__ void count_kernel(const int* __restrict__ batch, float* __restrict__ counts) {
    int n = blockIdx.x * blockDim.x + threadIdx.x;
    if (n < NN) atomicAdd(&counts[batch[n]], 1.f);
}
__global__ void pool_kernel(const float* __restrict__ x, const int* __restrict__ batch,
                            float* __restrict__ pooled) {
    long i = (long)blockIdx.x * blockDim.x + threadIdx.x;
    if (i >= (long)NN * 256) return;
    int n = i / 256, c = i % 256;
    atomicAdd(&pooled[batch[n] * 256 + c], x[i]);
}
__global__ void pool_div(float* __restrict__ pooled, const float* __restrict__ counts) {
    int i = blockIdx.x * blockDim.x + threadIdx.x;
    if (i >= GG * 256) return;
    int g = i / 256;
    pooled[i] /= fmaxf(counts[g], 1.f);
}

// ---------------- FC head ----------------
__global__ void fc_kernel(const float* __restrict__ in, const float* __restrict__ W,
                          const float* __restrict__ b, float* __restrict__ out,
                          int M, int N, int K) {
    int idx = blockIdx.x * blockDim.x + threadIdx.x;
    if (idx >= M * N) return;
    int r = idx / N, c = idx % N;
    float s = b[c];
    for (int k = 0; k < K; k++) s += in[r * K + k] * W[k * N + c];
    out[idx] = s;
}

__global__ void bn_small_relu(const float* __restrict__ in, const float* __restrict__ g,
                              const float* __restrict__ b, float* __restrict__ out, int C) {
    int c = blockIdx.x * blockDim.x + threadIdx.x;
    if (c >= C) return;
    float s = 0.f, sq = 0.f;
    for (int r = 0; r < GG; r++) { float v = in[r * C + c]; s += v; sq += v * v; }
    float mu = s / (float)GG;
    float rstd = rsqrtf(sq / (float)GG - mu * mu + 1e-5f);
    for (int r = 0; r < GG; r++) {
        float v = (in[r * C + c] - mu) * rstd * g[c] + b[c];
        out[r * C + c] = fmaxf(v, 0.f);
    }
}

__global__ void final_out(const float* __restrict__ z, const float* __restrict__ Wout,
                          const float* __restrict__ bout, float* __restrict__ out) {
    int g = blockIdx.x * blockDim.x + threadIdx.x;
    if (g >= GG) return;
    float s = bout[0];
    for (int k = 0; k < 256; k++) s += z[g * 256 + k] * Wout[k];
    out[g] = s;
}

// ---------------- host driver ----------------
static inline int cdiv(long a, int b) { return (int)((a + b - 1) / b); }

extern "C" void kernel_launch(void* const* d_in, const int* in_sizes, int n_in,
                              void* d_out, int out_size) {
    const float* x    = (const float*)d_in[0];
    const int*   esrc = (const int*)d_in[1];
    const int*   edst = (const int*)d_in[2];
    const int*   batch= (const int*)d_in[3];
    const float* W1   = (const float*)d_in[4];
    const float* a_s1 = (const float*)d_in[5];
    const float* a_d1 = (const float*)d_in[6];
    const float* b1   = (const float*)d_in[7];
    const float* g1   = (const float*)d_in[8];
    const float* be1  = (const float*)d_in[9];
    const float* W2   = (const float*)d_in[10];
    const float* a_s2 = (const float*)d_in[11];
    const float* a_d2 = (const float*)d_in[12];
    const float* b2   = (const float*)d_in[13];
    const float* g2   = (const float*)d_in[14];
    const float* be2  = (const float*)d_in[15];
    const float* Wf1  = (const float*)d_in[16];
    const float* bf1  = (const float*)d_in[17];
    const float* gf1  = (const float*)d_in[18];
    const float* bef1 = (const float*)d_in[19];
    const float* Wf2  = (const float*)d_in[20];
    const float* bf2  = (const float*)d_in[21];
    const float* gf2  = (const float*)d_in[22];
    const float* bef2 = (const float*)d_in[23];
    const float* Wout = (const float*)d_in[24];
    const float* bout = (const float*)d_in[25];
    float* out = (float*)d_out;

    float *h1, *agg1, *x2, *h2, *agg2, *x3;
    float *es1, *ed1, *den1, *es2, *ed2, *den2;
    unsigned *menc1, *menc2;
    float *bnsum, *bnsq, *mu, *rstd, *pooled, *counts, *z1, *z1n, *z2, *z2n;
    cudaGetSymbolAddress((void**)&h1, d_h1);
    cudaGetSymbolAddress((void**)&agg1, d_agg1);
    cudaGetSymbolAddress((void**)&x2, d_x2);
    cudaGetSymbolAddress((void**)&h2, d_h2);
    cudaGetSymbolAddress((void**)&agg2, d_agg2);
    cudaGetSymbolAddress((void**)&x3, d_x3);
    cudaGetSymbolAddress((void**)&es1, d_es1);
    cudaGetSymbolAddress((void**)&ed1, d_ed1);
    cudaGetSymbolAddress((void**)&den1, d_den1);
    cudaGetSymbolAddress((void**)&menc1, d_menc1);
    cudaGetSymbolAddress((void**)&es2, d_es2);
    cudaGetSymbolAddress((void**)&ed2, d_ed2);
    cudaGetSymbolAddress((void**)&den2, d_den2);
    cudaGetSymbolAddress((void**)&menc2, d_menc2);
    cudaGetSymbolAddress((void**)&bnsum, d_bnsum);
    cudaGetSymbolAddress((void**)&bnsq, d_bnsq);
    cudaGetSymbolAddress((void**)&mu, d_mu);
    cudaGetSymbolAddress((void**)&rstd, d_rstd);
    cudaGetSymbolAddress((void**)&pooled, d_pooled);
    cudaGetSymbolAddress((void**)&counts, d_counts);
    cudaGetSymbolAddress((void**)&z1, d_z1);
    cudaGetSymbolAddress((void**)&z1n, d_z1n);
    cudaGetSymbolAddress((void**)&z2, d_z2);
    cudaGetSymbolAddress((void**)&z2n, d_z2n);

    const int TB = 256;
    const int edge_total = EE + NN;

    // ===== layer 1 =====
    fillf<<<cdiv((long)NN * 128, TB), TB>>>(agg1, (long)NN * 128, 0.f);
    fillf<<<cdiv((long)NN * 2, TB), TB>>>(den1, (long)NN * 2, 0.f);
    fillf<<<cdiv((long)NN * 2, TB), TB>>>((float*)menc1, (long)NN * 2, 0.f);
    fillf<<<1, 256>>>(bnsum, 256, 0.f);
    fillf<<<1, 256>>>(bnsq, 256, 0.f);

    gemm_kernel<<<dim3(128 / 64, cdiv(NN, 64)), 256>>>(x, W1, h1, NN, 128, 64);
    attn_coef<<<cdiv(NN * 2, TB), TB>>>(h1, a_s1, a_d1, es1, ed1, NN, 64);
    edge_max<<<cdiv(edge_total, TB), TB>>>(esrc, edst, es1, ed1, menc1);
    edge_scatter<128, 64><<<cdiv((long)edge_total * 32, TB), TB>>>(esrc, edst, es1, ed1, menc1, h1, agg1, den1);
    gat_finalize<<<cdiv((long)NN * 128, TB), TB>>>(agg1, den1, b1, 128, 64);
    bn_stats_part<<<512, 128>>>(agg1, bnsum, bnsq, NN, 128);
    bn_finalize<<<1, 128>>>(bnsum, bnsq, mu, rstd, NN, 128);
    bn_apply_relu<<<cdiv((long)NN * 128, TB), TB>>>(agg1, mu, rstd, g1, be1, x2, (long)NN * 128, 128);

    // ===== layer 2 =====
    fillf<<<cdiv((long)NN * 256, TB), TB>>>(agg2, (long)NN * 256, 0.f);
    fillf<<<cdiv((long)NN * 2, TB), TB>>>(den2, (long)NN * 2, 0.f);
    fillf<<<cdiv((long)NN * 2, TB), TB>>>((float*)menc2, (long)NN * 2, 0.f);
    fillf<<<1, 256>>>(bnsum, 256, 0.f);
    fillf<<<1, 256>>>(bnsq, 256, 0.f);

    gemm_kernel<<<dim3(256 / 64, cdiv(NN, 64)), 256>>>(x2, W2, h2, NN, 256, 128);
    attn_coef<<<cdiv(NN * 2, TB), TB>>>(h2, a_s2, a_d2, es2, ed2, NN, 128);
    edge_max<<<cdiv(edge_total, TB), TB>>>(esrc, edst, es2, ed2, menc2);
    edge_scatter<256, 128><<<cdiv((long)edge_total * 32, TB), TB>>>(esrc, edst, es2, ed2, menc2, h2, agg2, den2);
    gat_finalize<<<cdiv((long)NN * 256, TB), TB>>>(agg2, den2, b2, 256, 128);
    bn_stats_part<<<512, 256>>>(agg2, bnsum, bnsq, NN, 256);
    bn_finalize<<<1, 256>>>(bnsum, bnsq, mu, rstd, NN, 256);
    bn_apply_relu<<<cdiv((long)NN * 256, TB), TB>>>(agg2, mu, rstd, g2, be2, x3, (long)NN * 256, 256);

    // ===== pooling =====
    fillf<<<cdiv((long)GG * 256, TB), TB>>>(pooled, (long)GG * 256, 0.f);
    fillf<<<1, GG>>>(counts, GG, 0.f);
    count_kernel<<<cdiv(NN, TB), TB>>>(batch, counts);
    pool_kernel<<<cdiv((long)NN * 256, TB), TB>>>(x3, batch, pooled);
    pool_div<<<cdiv(GG * 256, TB), TB>>>(pooled, counts);

    // ===== FC head =====
    fc_kernel<<<cdiv(GG * 512, TB), TB>>>(pooled, Wf1, bf1, z1, GG, 512, 256);
    bn_small_relu<<<2, 256>>>(z1, gf1, bef1, z1n, 512);
    fc_kernel<<<cdiv(GG * 256, TB), TB>>>(z1n, Wf2, bf2, z2, GG, 256, 512);
    bn_small_relu<<<1, 256>>>(z2, gf2, bef2, z2n, 256);
    final_out<<<1, GG>>>(z2n, Wout, bout, out);
}

// round 2
// speedup vs baseline: 1.8623x; 1.8623x over previous
#include <cuda_runtime.h>
#include <cuda_bf16.h>

// Problem constants (fixed by the reference)
#define NN 50000
#define EE 500000
#define HH 2
#define GG 128

// ---------------- scratch (static __device__ globals; no runtime alloc) ----------------
__device__ float d_h1[NN * 128];     // layer1 linear out
__device__ float d_y1[NN * 128];     // layer1 GAT out (post bias)
__device__ float d_x2[NN * 128];     // layer1 post-BN+relu (layer2 input)
__device__ float d_h2[NN * 256];     // layer2 linear out
__device__ float d_y2[NN * 256];
__device__ float d_x3[NN * 256];     // layer2 post-BN+relu
__device__ float d_es1[NN * 2], d_ed1[NN * 2];
__device__ float d_es2[NN * 2], d_ed2[NN * 2];
__device__ float d_nmax[NN * 2], d_nden[NN * 2];
__device__ int   d_deg[NN], d_off[NN + 1], d_cursor[NN];
__device__ int   d_csrc[EE + NN];
__device__ int   d_gstart[GG + 1];
__device__ float d_bnsum[256], d_bnsq[256], d_mu[256], d_rstd[256];
__device__ float d_pooled[GG * 256];
__device__ float d_z1[GG * 512], d_z1n[GG * 512];
__device__ float d_z2[GG * 256], d_z2n[GG * 256];

// ---------------- small fills ----------------
__global__ void fillf(float* p, long n, float v) {
    long i = (long)blockIdx.x * blockDim.x + threadIdx.x;
    if (i < n) p[i] = v;
}
__global__ void fill_int(int* p, int n, int v) {
    int i = blockIdx.x * blockDim.x + threadIdx.x;
    if (i < n) p[i] = v;
}

// ---------------- CSR build ----------------
__global__ void count_deg(const int* __restrict__ dst, int* __restrict__ deg) {
    int e = blockIdx.x * blockDim.x + threadIdx.x;
    if (e < EE) atomicAdd(&deg[dst[e]], 1);
}

// single-block scan: 1024 threads, each handles ceil(NN/1024) entries
__global__ void scan_offsets(const int* __restrict__ deg, int* __restrict__ off,
                             int* __restrict__ cursor) {
    __shared__ int part[1024];
    const int CH = (NN + 1023) / 1024;
    int t = threadIdx.x;
    int base = t * CH;
    int s = 0;
    for (int i = 0; i < CH; i++) {
        int idx = base + i;
        if (idx < NN) s += deg[idx];
    }
    part[t] = s;
    __syncthreads();
    for (int d = 1; d < 1024; d <<= 1) {
        int v = (t >= d) ? part[t - d] : 0;
        __syncthreads();
        part[t] += v;
        __syncthreads();
    }
    int run = (t == 0) ? 0 : part[t - 1];
    for (int i = 0; i < CH; i++) {
        int idx = base + i;
        if (idx < NN) {
            off[idx] = run;
            cursor[idx] = run;
            run += deg[idx];
        }
    }
    if (t == 1023) off[NN] = part[1023];
}

__global__ void csr_fill_edges(const int* __restrict__ src, const int* __restrict__ dst,
                               int* __restrict__ cursor, int* __restrict__ csrc) {
    int e = blockIdx.x * blockDim.x + threadIdx.x;
    if (e >= EE) return;
    int t = dst[e];
    int p = atomicAdd(&cursor[t], 1);
    csrc[p] = src[e];
}
__global__ void csr_fill_loops(int* __restrict__ cursor, int* __restrict__ csrc) {
    int n = blockIdx.x * blockDim.x + threadIdx.x;
    if (n >= NN) return;
    int p = atomicAdd(&cursor[n], 1);
    csrc[p] = n;
}

// ---------------- tiled fp32 GEMM: C[M,N] = A[M,K] @ B[K,N] ----------------
// BM=128, BN=64, BK=16, 256 threads, 8x4 microtile. Requires N%64==0, K%16==0.
__global__ void gemm128(const float* __restrict__ A, const float* __restrict__ B,
                        float* __restrict__ C, int M, int N, int K) {
    __shared__ float As[16][128];
    __shared__ float Bs[16][64];
    const int brow = blockIdx.y * 128;
    const int bcol = blockIdx.x * 64;
    const int tid = threadIdx.x;
    const int tr = tid / 16, tc = tid % 16;
    float acc[8][4] = {};
    for (int k0 = 0; k0 < K; k0 += 16) {
        #pragma unroll
        for (int i = tid; i < 512; i += 256) {   // 128 rows x 4 float4
            int r = i / 4, cc = (i % 4) * 4;
            int gr = brow + r;
            float4 v = (gr < M) ? *(const float4*)(A + (long)gr * K + k0 + cc)
                                : make_float4(0.f, 0.f, 0.f, 0.f);
            As[cc + 0][r] = v.x;
            As[cc + 1][r] = v.y;
            As[cc + 2][r] = v.z;
            As[cc + 3][r] = v.w;
        }
        {
            int r = tid / 16, cc = (tid % 16) * 4;
            *(float4*)&Bs[r][cc] = *(const float4*)(B + (long)(k0 + r) * N + bcol + cc);
        }
        __syncthreads();
        #pragma unroll
        for (int kk = 0; kk < 16; kk++) {
            float4 a0 = *(const float4*)&As[kk][tr * 8];
            float4 a1 = *(const float4*)&As[kk][tr * 8 + 4];
            float4 bb = *(const float4*)&Bs[kk][tc * 4];
            float a[8] = {a0.x, a0.y, a0.z, a0.w, a1.x, a1.y, a1.z, a1.w};
            float bv[4] = {bb.x, bb.y, bb.z, bb.w};
            #pragma unroll
            for (int i = 0; i < 8; i++)
                #pragma unroll
                for (int j = 0; j < 4; j++) acc[i][j] += a[i] * bv[j];
        }
        __syncthreads();
    }
    #pragma unroll
    for (int i = 0; i < 8; i++) {
        int gr = brow + tr * 8 + i;
        if (gr < M)
            *(float4*)(C + (long)gr * N + bcol + tc * 4) =
                make_float4(acc[i][0], acc[i][1], acc[i][2], acc[i][3]);
    }
}

// ---------------- per-node attention coefficients ----------------
__global__ void attn_coef(const float* __restrict__ h, const float* __restrict__ a_s,
                          const float* __restrict__ a_d, float* __restrict__ es,
                          float* __restrict__ ed, int D) {
    int idx = blockIdx.x * blockDim.x + threadIdx.x;
    if (idx >= NN * HH) return;
    int n = idx / HH, hh = idx % HH;
    const float* hp = h + (long)n * HH * D + hh * D;
    const float* as = a_s + hh * D;
    const float* ad = a_d + hh * D;
    float s1 = 0.f, s2 = 0.f;
    for (int d = 0; d < D; d++) {
        float v = hp[d];
        s1 += v * as[d];
        s2 += v * ad[d];
    }
    es[idx] = s1;
    ed[idx] = s2;
}

// ---------------- per-node softmax stats (max + denom) via CSR gather ----------------
__global__ void node_stats(const int* __restrict__ off, const int* __restrict__ csrc,
                           const float* __restrict__ es, const float* __restrict__ ed,
                           float* __restrict__ nmax, float* __restrict__ nden) {
    int warp = (blockIdx.x * blockDim.x + threadIdx.x) >> 5;
    int lane = threadIdx.x & 31;
    if (warp >= NN) return;
    int t = warp;
    int b = off[t], e = off[t + 1];
    float ed0 = ed[t * 2], ed1 = ed[t * 2 + 1];
    float m0 = -1e30f, m1 = -1e30f;
    for (int i = b + lane; i < e; i += 32) {
        int s = csrc[i];
        float2 esv = *(const float2*)(es + s * 2);
        float v0 = esv.x + ed0; v0 = v0 > 0.f ? v0 : 0.2f * v0;
        float v1 = esv.y + ed1; v1 = v1 > 0.f ? v1 : 0.2f * v1;
        m0 = fmaxf(m0, v0);
        m1 = fmaxf(m1, v1);
    }
    #pragma unroll
    for (int o = 16; o; o >>= 1) {
        m0 = fmaxf(m0, __shfl_xor_sync(0xffffffffu, m0, o));
        m1 = fmaxf(m1, __shfl_xor_sync(0xffffffffu, m1, o));
    }
    float s0 = 0.f, s1 = 0.f;
    for (int i = b + lane; i < e; i += 32) {
        int s = csrc[i];
        float2 esv = *(const float2*)(es + s * 2);
        float v0 = esv.x + ed0; v0 = v0 > 0.f ? v0 : 0.2f * v0;
        float v1 = esv.y + ed1; v1 = v1 > 0.f ? v1 : 0.2f * v1;
        s0 += __expf(v0 - m0);
        s1 += __expf(v1 - m1);
    }
    #pragma unroll
    for (int o = 16; o; o >>= 1) {
        s0 += __shfl_xor_sync(0xffffffffu, s0, o);
        s1 += __shfl_xor_sync(0xffffffffu, s1, o);
    }
    if (lane == 0) {
        nmax[t * 2] = m0;
        nmax[t * 2 + 1] = m1;
        nden[t * 2] = s0;
        nden[t * 2 + 1] = s1;
    }
}

// ---------------- gather aggregation: one warp per dst node, no atomics ----------------
template <int C>
__global__ void node_aggregate(const int* __restrict__ off, const int* __restrict__ csrc,
                               const float* __restrict__ es, const float* __restrict__ ed,
                               const float* __restrict__ nmax, const float* __restrict__ nden,
                               const float* __restrict__ h, const float* __restrict__ bias,
                               float* __restrict__ outp) {
    int warp = (blockIdx.x * blockDim.x + threadIdx.x) >> 5;
    int lane = threadIdx.x & 31;
    if (warp >= NN) return;
    int t = warp;
    int b = off[t], e = off[t + 1];
    float ed0 = ed[t * 2], ed1 = ed[t * 2 + 1];
    float m0 = nmax[t * 2], m1 = nmax[t * 2 + 1];
    float r0 = 1.f / (nden[t * 2] + 1e-16f);
    float r1 = 1.f / (nden[t * 2 + 1] + 1e-16f);
    float4 acc0 = make_float4(0.f, 0.f, 0.f, 0.f);
    float4 acc1 = make_float4(0.f, 0.f, 0.f, 0.f);

    for (int base = b; base < e; base += 32) {
        int n = min(32, e - base);
        float w0 = 0.f, w1 = 0.f;
        int sreg = 0;
        if (lane < n) {
            sreg = csrc[base + lane];
            float2 esv = *(const float2*)(es + sreg * 2);
            float v0 = esv.x + ed0; v0 = v0 > 0.f ? v0 : 0.2f * v0;
            float v1 = esv.y + ed1; v1 = v1 > 0.f ? v1 : 0.2f * v1;
            w0 = __expf(v0 - m0);
            w1 = __expf(v1 - m1);
        }
        for (int j = 0; j < n; j++) {
            int s = __shfl_sync(0xffffffffu, sreg, j);
            float ww0 = __shfl_sync(0xffffffffu, w0, j);
            float ww1 = __shfl_sync(0xffffffffu, w1, j);
            const float* hp = h + (long)s * C;
            if (C == 128) {
                float4 hv = *(const float4*)(hp + lane * 4);
                float w = (lane < 16) ? ww0 : ww1;   // channels 0..63 head0, 64..127 head1
                acc0.x += hv.x * w; acc0.y += hv.y * w;
                acc0.z += hv.z * w; acc0.w += hv.w * w;
            } else {
                float4 hv0 = *(const float4*)(hp + lane * 4);
                float4 hv1 = *(const float4*)(hp + 128 + lane * 4);
                acc0.x += hv0.x * ww0; acc0.y += hv0.y * ww0;
                acc0.z += hv0.z * ww0; acc0.w += hv0.w * ww0;
                acc1.x += hv1.x * ww1; acc1.y += hv1.y * ww1;
                acc1.z += hv1.z * ww1; acc1.w += hv1.w * ww1;
            }
        }
    }
    if (C == 128) {
        float r = (lane < 16) ? r0 : r1;
        int c = lane * 4;
        const float4 bb = *(const float4*)(bias + c);
        float4 o = make_float4(acc0.x * r + bb.x, acc0.y * r + bb.y,
                               acc0.z * r + bb.z, acc0.w * r + bb.w);
        *(float4*)(outp + (long)t * C + c) = o;
    } else {
        int c0 = lane * 4, c1 = 128 + lane * 4;
        const float4 b0 = *(const float4*)(bias + c0);
        const float4 b1 = *(const float4*)(bias + c1);
        *(float4*)(outp + (long)t * C + c0) =
            make_float4(acc0.x * r0 + b0.x, acc0.y * r0 + b0.y,
                        acc0.z * r0 + b0.z, acc0.w * r0 + b0.w);
        *(float4*)(outp + (long)t * C + c1) =
            make_float4(acc1.x * r1 + b1.x, acc1.y * r1 + b1.y,
                        acc1.z * r1 + b1.z, acc1.w * r1 + b1.w);
    }
}

// ---------------- batchnorm over N rows ----------------
__global__ void bn_stats_part(const float* __restrict__ x, float* __restrict__ gsum,
                              float* __restrict__ gsq, int rows, int C) {
    int c = threadIdx.x;  // blockDim.x == C
    float s = 0.f, sq = 0.f;
    for (int r = blockIdx.x; r < rows; r += gridDim.x) {
        float v = x[(long)r * C + c];
        s += v;
        sq += v * v;
    }
    atomicAdd(&gsum[c], s);
    atomicAdd(&gsq[c], sq);
}

__global__ void bn_finalize(const float* __restrict__ gsum, const float* __restrict__ gsq,
                            float* __restrict__ mu, float* __restrict__ rstd, int rows, int C) {
    int c = blockIdx.x * blockDim.x + threadIdx.x;
    if (c >= C) return;
    float m = gsum[c] / (float)rows;
    float var = gsq[c] / (float)rows - m * m;
    mu[c] = m;
    rstd[c] = rsqrtf(var + 1e-5f);
}

__global__ void bn_apply_relu(const float* __restrict__ in, const float* __restrict__ mu,
                              const float* __restrict__ rstd, const float* __restrict__ g,
                              const float* __restrict__ b, float* __restrict__ out,
                              long total, int C) {
    long i = (long)blockIdx.x * blockDim.x + threadIdx.x;
    if (i >= total) return;
    int c = i % C;
    float v = (in[i] - mu[c]) * rstd[c] * g[c] + b[c];
    out[i] = fmaxf(v, 0.f);
}

// ---------------- pooling (batch sorted -> contiguous ranges) ----------------
__global__ void graph_bounds(const int* __restrict__ batch, int* __restrict__ gstart) {
    int g = blockIdx.x * blockDim.x + threadIdx.x;
    if (g > GG) return;
    int lo = 0, hi = NN;
    while (lo < hi) {
        int mid = (lo + hi) >> 1;
        if (batch[mid] < g) lo = mid + 1; else hi = mid;
    }
    gstart[g] = lo;
}

__global__ void pool_sum(const float* __restrict__ x, const int* __restrict__ gstart,
                         float* __restrict__ pooled) {
    int g = blockIdx.x;
    int seg = blockIdx.y;
    int c = threadIdx.x;  // 256
    int b = gstart[g], e = gstart[g + 1];
    int len = e - b;
    int per = (len + 7) / 8;
    int rb = b + seg * per;
    int re = min(rb + per, e);
    float s = 0.f;
    for (int r = rb; r < re; r++) s += x[(long)r * 256 + c];
    atomicAdd(&pooled[g * 256 + c], s);
}

__global__ void pool_div(float* __restrict__ pooled, const int* __restrict__ gstart) {
    int i = blockIdx.x * blockDim.x + threadIdx.x;
    if (i >= GG * 256) return;
    int g = i / 256;
    float cnt = (float)(gstart[g + 1] - gstart[g]);
    pooled[i] /= fmaxf(cnt, 1.f);
}

// ---------------- FC head ----------------
__global__ void fc_kernel(const float* __restrict__ in, const float* __restrict__ W,
                          const float* __restrict__ b, float* __restrict__ out,
                          int M, int N, int K) {
    int idx = blockIdx.x * blockDim.x + threadIdx.x;
    if (idx >= M * N) return;
    int r = idx / N, c = idx % N;
    float s = b[c];
    for (int k = 0; k < K; k++) s += in[r * K + k] * W[k * N + c];
    out[idx] = s;
}

__global__ void bn_small_relu(const float* __restrict__ in, const float* __restrict__ g,
                              const float* __restrict__ b, float* __restrict__ out, int C) {
    int c = blockIdx.x * blockDim.x + threadIdx.x;
    if (c >= C) return;
    float s = 0.f, sq = 0.f;
    for (int r = 0; r < GG; r++) {
        float v = in[r * C + c];
        s += v;
        sq += v * v;
    }
    float mu = s / (float)GG;
    float rstd = rsqrtf(sq / (float)GG - mu * mu + 1e-5f);
    for (int r = 0; r < GG; r++) {
        float v = (in[r * C + c] - mu) * rstd * g[c] + b[c];
        out[r * C + c] = fmaxf(v, 0.f);
    }
}

__global__ void final_out(const float* __restrict__ z, const float* __restrict__ Wout,
                          const float* __restrict__ bout, float* __restrict__ out) {
    int g = blockIdx.x * blockDim.x + threadIdx.x;
    if (g >= GG) return;
    float s = bout[0];
    for (int k = 0; k < 256; k++) s += z[g * 256 + k] * Wout[k];
    out[g] = s;
}

// ---------------- host driver ----------------
static inline int cdiv(long a, int b) { return (int)((a + b - 1) / b); }

extern "C" void kernel_launch(void* const* d_in, const int* in_sizes, int n_in,
                              void* d_out, int out_size) {
    const float* x    = (const float*)d_in[0];
    const int*   esrc = (const int*)d_in[1];
    const int*   edst = (const int*)d_in[2];
    const int*   batch= (const int*)d_in[3];
    const float* W1   = (const float*)d_in[4];
    const float* a_s1 = (const float*)d_in[5];
    const float* a_d1 = (const float*)d_in[6];
    const float* b1   = (const float*)d_in[7];
    const float* g1   = (const float*)d_in[8];
    const float* be1  = (const float*)d_in[9];
    const float* W2   = (const float*)d_in[10];
    const float* a_s2 = (const float*)d_in[11];
    const float* a_d2 = (const float*)d_in[12];
    const float* b2   = (const float*)d_in[13];
    const float* g2   = (const float*)d_in[14];
    const float* be2  = (const float*)d_in[15];
    const float* Wf1  = (const float*)d_in[16];
    const float* bf1  = (const float*)d_in[17];
    const float* gf1  = (const float*)d_in[18];
    const float* bef1 = (const float*)d_in[19];
    const float* Wf2  = (const float*)d_in[20];
    const float* bf2  = (const float*)d_in[21];
    const float* gf2  = (const float*)d_in[22];
    const float* bef2 = (const float*)d_in[23];
    const float* Wout = (const float*)d_in[24];
    const float* bout = (const float*)d_in[25];
    float* out = (float*)d_out;

    float *h1, *y1, *x2, *h2, *y2, *x3;
    float *es1, *ed1, *es2, *ed2, *nmax, *nden;
    int *deg, *off, *cursor, *csrc, *gstart;
    float *bnsum, *bnsq, *mu, *rstd, *pooled, *z1, *z1n, *z2, *z2n;
    cudaGetSymbolAddress((void**)&h1, d_h1);
    cudaGetSymbolAddress((void**)&y1, d_y1);
    cudaGetSymbolAddress((void**)&x2, d_x2);
    cudaGetSymbolAddress((void**)&h2, d_h2);
    cudaGetSymbolAddress((void**)&y2, d_y2);
    cudaGetSymbolAddress((void**)&x3, d_x3);
    cudaGetSymbolAddress((void**)&es1, d_es1);
    cudaGetSymbolAddress((void**)&ed1, d_ed1);
    cudaGetSymbolAddress((void**)&es2, d_es2);
    cudaGetSymbolAddress((void**)&ed2, d_ed2);
    cudaGetSymbolAddress((void**)&nmax, d_nmax);
    cudaGetSymbolAddress((void**)&nden, d_nden);
    cudaGetSymbolAddress((void**)&deg, d_deg);
    cudaGetSymbolAddress((void**)&off, d_off);
    cudaGetSymbolAddress((void**)&cursor, d_cursor);
    cudaGetSymbolAddress((void**)&csrc, d_csrc);
    cudaGetSymbolAddress((void**)&gstart, d_gstart);
    cudaGetSymbolAddress((void**)&bnsum, d_bnsum);
    cudaGetSymbolAddress((void**)&bnsq, d_bnsq);
    cudaGetSymbolAddress((void**)&mu, d_mu);
    cudaGetSymbolAddress((void**)&rstd, d_rstd);
    cudaGetSymbolAddress((void**)&pooled, d_pooled);
    cudaGetSymbolAddress((void**)&z1, d_z1);
    cudaGetSymbolAddress((void**)&z1n, d_z1n);
    cudaGetSymbolAddress((void**)&z2, d_z2);
    cudaGetSymbolAddress((void**)&z2n, d_z2n);

    const int TB = 256;

    // ===== CSR build (shared by both layers) =====
    fill_int<<<cdiv(NN, TB), TB>>>(deg, NN, 1);   // self-loop counts as 1
    count_deg<<<cdiv(EE, TB), TB>>>(edst, deg);
    scan_offsets<<<1, 1024>>>(deg, off, cursor);
    csr_fill_edges<<<cdiv(EE, TB), TB>>>(esrc, edst, cursor, csrc);
    csr_fill_loops<<<cdiv(NN, TB), TB>>>(cursor, csrc);
    graph_bounds<<<1, 256>>>(batch, gstart);

    // ===== layer 1 =====
    fillf<<<1, 256>>>(bnsum, 256, 0.f);
    fillf<<<1, 256>>>(bnsq, 256, 0.f);
    gemm128<<<dim3(128 / 64, cdiv(NN, 128)), 256>>>(x, W1, h1, NN, 128, 64);
    attn_coef<<<cdiv(NN * 2, TB), TB>>>(h1, a_s1, a_d1, es1, ed1, 64);
    node_stats<<<cdiv(NN * 32, TB), TB>>>(off, csrc, es1, ed1, nmax, nden);
    node_aggregate<128><<<cdiv(NN * 32, TB), TB>>>(off, csrc, es1, ed1, nmax, nden, h1, b1, y1);
    bn_stats_part<<<512, 128>>>(y1, bnsum, bnsq, NN, 128);
    bn_finalize<<<1, 128>>>(bnsum, bnsq, mu, rstd, NN, 128);
    bn_apply_relu<<<cdiv((long)NN * 128, TB), TB>>>(y1, mu, rstd, g1, be1, x2, (long)NN * 128, 128);

    // ===== layer 2 =====
    fillf<<<1, 256>>>(bnsum, 256, 0.f);
    fillf<<<1, 256>>>(bnsq, 256, 0.f);
    gemm128<<<dim3(256 / 64, cdiv(NN, 128)), 256>>>(x2, W2, h2, NN, 256, 128);
    attn_coef<<<cdiv(NN * 2, TB), TB>>>(h2, a_s2, a_d2, es2, ed2, 128);
    node_stats<<<cdiv(NN * 32, TB), TB>>>(off, csrc, es2, ed2, nmax, nden);
    node_aggregate<256><<<cdiv(NN * 32, TB), TB>>>(off, csrc, es2, ed2, nmax, nden, h2, b2, y2);
    bn_stats_part<<<512, 256>>>(y2, bnsum, bnsq, NN, 256);
    bn_finalize<<<1, 256>>>(bnsum, bnsq, mu, rstd, NN, 256);
    bn_apply_relu<<<cdiv((long)NN * 256, TB), TB>>>(y2, mu, rstd, g2, be2, x3, (long)NN * 256, 256);

    // ===== pooling =====
    fillf<<<cdiv(GG * 256, TB), TB>>>(pooled, GG * 256, 0.f);
    pool_sum<<<dim3(GG, 8), 256>>>(x3, gstart, pooled);
    pool_div<<<cdiv(GG * 256, TB), TB>>>(pooled, gstart);

    // ===== FC head =====
    fc_kernel<<<cdiv(GG * 512, TB), TB>>>(pooled, Wf1, bf1, z1, GG, 512, 256);
    bn_small_relu<<<2, 256>>>(z1, gf1, bef1, z1n, 512);
    fc_kernel<<<cdiv(GG * 256, TB), TB>>>(z1n, Wf2, bf2, z2, GG, 256, 512);
    bn_small_relu<<<1, 256>>>(z2, gf2, bef2, z2n, 256);
    final_out<<<1, GG>>>(z2n, Wout, bout, out);
}

// round 4
// speedup vs baseline: 2.0418x; 1.0964x over previous
#include <cuda_runtime.h>
#include <cuda_bf16.h>

// Problem constants (fixed by the reference)
#define NN 50000
#define EE 500000
#define HH 2
#define GG 128

// ---------------- scratch (static __device__ globals; no runtime alloc) ----------------
__device__ float d_h1[NN * 128];     // layer1 linear out
__device__ float d_y1[NN * 128];     // layer1 GAT out (post bias)
__device__ float d_x2[NN * 128];     // layer1 post-BN+relu (layer2 input)
__device__ float d_h2[NN * 256];     // layer2 linear out
__device__ float d_y2[NN * 256];
__device__ float d_x3[NN * 256];     // layer2 post-BN+relu
__device__ float d_es1[NN * 2], d_ed1[NN * 2];
__device__ float d_es2[NN * 2], d_ed2[NN * 2];
__device__ float d_nden[NN * 2];
__device__ float d_ew[(EE + NN) * 2];   // per-edge unnormalized softmax weights (CSR order)
__device__ int   d_deg[NN], d_off[NN + 1], d_cursor[NN];
__device__ int   d_csrc[EE + NN];
__device__ int   d_gstart[GG + 1];
__device__ float d_bnsum[256], d_bnsq[256], d_mu[256], d_rstd[256];
__device__ float d_pooled[GG * 256];
__device__ float d_z1[GG * 512], d_z1n[GG * 512];
__device__ float d_z2[GG * 256], d_z2n[GG * 256];

// ---------------- small fills ----------------
__global__ void fillf(float* p, long n, float v) {
    long i = (long)blockIdx.x * blockDim.x + threadIdx.x;
    if (i < n) p[i] = v;
}
__global__ void fill_int(int* p, int n, int v) {
    int i = blockIdx.x * blockDim.x + threadIdx.x;
    if (i < n) p[i] = v;
}

// ---------------- CSR build ----------------
__global__ void count_deg(const int* __restrict__ dst, int* __restrict__ deg) {
    int e = blockIdx.x * blockDim.x + threadIdx.x;
    if (e < EE) atomicAdd(&deg[dst[e]], 1);
}

__global__ void scan_offsets(const int* __restrict__ deg, int* __restrict__ off,
                             int* __restrict__ cursor) {
    __shared__ int part[1024];
    const int CH = (NN + 1023) / 1024;
    int t = threadIdx.x;
    int base = t * CH;
    int s = 0;
    for (int i = 0; i < CH; i++) {
        int idx = base + i;
        if (idx < NN) s += deg[idx];
    }
    part[t] = s;
    __syncthreads();
    for (int d = 1; d < 1024; d <<= 1) {
        int v = (t >= d) ? part[t - d] : 0;
        __syncthreads();
        part[t] += v;
        __syncthreads();
    }
    int run = (t == 0) ? 0 : part[t - 1];
    for (int i = 0; i < CH; i++) {
        int idx = base + i;
        if (idx < NN) {
            off[idx] = run;
            cursor[idx] = run;
            run += deg[idx];
        }
    }
    if (t == 1023) off[NN] = part[1023];
}

__global__ void csr_fill_edges(const int* __restrict__ src, const int* __restrict__ dst,
                               int* __restrict__ cursor, int* __restrict__ csrc) {
    int e = blockIdx.x * blockDim.x + threadIdx.x;
    if (e >= EE) return;
    int t = dst[e];
    int p = atomicAdd(&cursor[t], 1);
    csrc[p] = src[e];
}
__global__ void csr_fill_loops(int* __restrict__ cursor, int* __restrict__ csrc) {
    int n = blockIdx.x * blockDim.x + threadIdx.x;
    if (n >= NN) return;
    int p = atomicAdd(&cursor[n], 1);
    csrc[p] = n;
}

// ---------------- tf32 tensor-core GEMM: C[M,N] = A[M,K] @ B[K,N] ----------------
// BM=128, BN=64, BK=16, 256 threads (8 warps, 4x2). Warp tile 32x32 via m16n8k8.
__device__ __forceinline__ unsigned f2tf(float f) {
    unsigned r;
    asm("cvt.rna.tf32.f32 %0, %1;" : "=r"(r) : "f"(f));
    return r;
}
__device__ __forceinline__ void mma_tf32(float4& c, const unsigned* a, const unsigned* b) {
    asm volatile(
        "mma.sync.aligned.m16n8k8.row.col.f32.tf32.tf32.f32 "
        "{%0,%1,%2,%3}, {%4,%5,%6,%7}, {%8,%9}, {%0,%1,%2,%3};"
        : "+f"(c.x), "+f"(c.y), "+f"(c.z), "+f"(c.w)
        : "r"(a[0]), "r"(a[1]), "r"(a[2]), "r"(a[3]), "r"(b[0]), "r"(b[1]));
}

__global__ void gemm_tf32(const float* __restrict__ A, const float* __restrict__ B,
                          float* __restrict__ C, int M, int N, int K) {
    __shared__ unsigned As[128][17];   // pad 17 -> conflict-free fragment loads
    __shared__ unsigned Bs[16][72];    // pad 72 -> conflict-free fragment loads
    const int brow = blockIdx.y * 128;
    const int bcol = blockIdx.x * 64;
    const int tid = threadIdx.x;
    const int w = tid >> 5, l = tid & 31;
    const int wm = w & 3, wn = w >> 2;          // 4 (m) x 2 (n) warps
    const int mbase = wm * 32, nbase = wn * 32;
    const int g = l >> 2, tg = l & 3;           // groupID, thread-in-group
    float4 acc[2][4];
    #pragma unroll
    for (int i = 0; i < 2; i++)
        #pragma unroll
        for (int j = 0; j < 4; j++) acc[i][j] = make_float4(0.f, 0.f, 0.f, 0.f);

    for (int k0 = 0; k0 < K; k0 += 16) {
        // stage A tile 128x16 (converted to tf32 bits)
        #pragma unroll
        for (int i = tid; i < 512; i += 256) {
            int r = i >> 2, c4 = (i & 3) * 4;
            int gr = brow + r;
            float4 v = (gr < M) ? *(const float4*)(A + (long)gr * K + k0 + c4)
                                : make_float4(0.f, 0.f, 0.f, 0.f);
            As[r][c4 + 0] = f2tf(v.x);
            As[r][c4 + 1] = f2tf(v.y);
            As[r][c4 + 2] = f2tf(v.z);
            As[r][c4 + 3] = f2tf(v.w);
        }
        // stage B tile 16x64
        {
            int r = tid >> 4, c4 = (tid & 15) * 4;
            float4 v = *(const float4*)(B + (long)(k0 + r) * N + bcol + c4);
            Bs[r][c4 + 0] = f2tf(v.x);
            Bs[r][c4 + 1] = f2tf(v.y);
            Bs[r][c4 + 2] = f2tf(v.z);
            Bs[r][c4 + 3] = f2tf(v.w);
        }
        __syncthreads();
        #pragma unroll
        for (int k8 = 0; k8 < 16; k8 += 8) {
            unsigned af[2][4], bf[4][2];
            #pragma unroll
            for (int mt = 0; mt < 2; mt++) {
                int r0 = mbase + mt * 16 + g;
                int c = k8 + tg;
                af[mt][0] = As[r0][c];
                af[mt][1] = As[r0 + 8][c];
                af[mt][2] = As[r0][c + 4];
                af[mt][3] = As[r0 + 8][c + 4];
            }
            #pragma unroll
            for (int nt = 0; nt < 4; nt++) {
                int cb = nbase + nt * 8 + g;
                int rb = k8 + tg;
                bf[nt][0] = Bs[rb][cb];
                bf[nt][1] = Bs[rb + 4][cb];
            }
            #pragma unroll
            for (int mt = 0; mt < 2; mt++)
                #pragma unroll
                for (int nt = 0; nt < 4; nt++) mma_tf32(acc[mt][nt], af[mt], bf[nt]);
        }
        __syncthreads();
    }
    // epilogue
    #pragma unroll
    for (int mt = 0; mt < 2; mt++) {
        #pragma unroll
        for (int nt = 0; nt < 4; nt++) {
            int row = brow + mbase + mt * 16 + g;
            int col = bcol + nbase + nt * 8 + 2 * tg;
            if (row < M)
                *(float2*)(C + (long)row * N + col) = make_float2(acc[mt][nt].x, acc[mt][nt].y);
            if (row + 8 < M)
                *(float2*)(C + (long)(row + 8) * N + col) = make_float2(acc[mt][nt].z, acc[mt][nt].w);
        }
    }
}

// ---------------- per-node attention coefficients ----------------
__global__ void attn_coef(const float* __restrict__ h, const float* __restrict__ a_s,
                          const float* __restrict__ a_d, float* __restrict__ es,
                          float* __restrict__ ed, int D) {
    int idx = blockIdx.x * blockDim.x + threadIdx.x;
    if (idx >= NN * HH) return;
    int n = idx / HH, hh = idx % HH;
    const float* hp = h + (long)n * HH * D + hh * D;
    const float* as = a_s + hh * D;
    const float* ad = a_d + hh * D;
    float s1 = 0.f, s2 = 0.f;
    for (int d = 0; d < D; d++) {
        float v = hp[d];
        s1 += v * as[d];
        s2 += v * ad[d];
    }
    es[idx] = s1;
    ed[idx] = s2;
}

// ---------------- softmax stats: per-node max+denom, write per-edge weights ----------------
__global__ void node_stats(const int* __restrict__ off, const int* __restrict__ csrc,
                           const float* __restrict__ es, const float* __restrict__ ed,
                           float* __restrict__ nden, float2* __restrict__ ew) {
    int warp = (blockIdx.x * blockDim.x + threadIdx.x) >> 5;
    int lane = threadIdx.x & 31;
    if (warp >= NN) return;
    int t = warp;
    int b = off[t], e = off[t + 1];
    float ed0 = ed[t * 2], ed1 = ed[t * 2 + 1];
    float m0 = -1e30f, m1 = -1e30f;
    for (int i = b + lane; i < e; i += 32) {
        int s = csrc[i];
        float2 esv = *(const float2*)(es + s * 2);
        float v0 = esv.x + ed0; v0 = v0 > 0.f ? v0 : 0.2f * v0;
        float v1 = esv.y + ed1; v1 = v1 > 0.f ? v1 : 0.2f * v1;
        m0 = fmaxf(m0, v0);
        m1 = fmaxf(m1, v1);
    }
    #pragma unroll
    for (int o = 16; o; o >>= 1) {
        m0 = fmaxf(m0, __shfl_xor_sync(0xffffffffu, m0, o));
        m1 = fmaxf(m1, __shfl_xor_sync(0xffffffffu, m1, o));
    }
    float s0 = 0.f, s1 = 0.f;
    for (int i = b + lane; i < e; i += 32) {
        int s = csrc[i];
        float2 esv = *(const float2*)(es + s * 2);
        float v0 = esv.x + ed0; v0 = v0 > 0.f ? v0 : 0.2f * v0;
        float v1 = esv.y + ed1; v1 = v1 > 0.f ? v1 : 0.2f * v1;
        float w0 = __expf(v0 - m0);
        float w1 = __expf(v1 - m1);
        ew[i] = make_float2(w0, w1);
        s0 += w0;
        s1 += w1;
    }
    #pragma unroll
    for (int o = 16; o; o >>= 1) {
        s0 += __shfl_xor_sync(0xffffffffu, s0, o);
        s1 += __shfl_xor_sync(0xffffffffu, s1, o);
    }
    if (lane == 0) {
        nden[t * 2] = s0;
        nden[t * 2 + 1] = s1;
    }
}

// ---------------- gather aggregation: one warp per dst node, no atomics ----------------
template <int C>
__global__ void node_aggregate(const int* __restrict__ off, const int* __restrict__ csrc,
                               const float2* __restrict__ ew, const float* __restrict__ nden,
                               const float* __restrict__ h, const float* __restrict__ bias,
                               float* __restrict__ outp) {
    int warp = (blockIdx.x * blockDim.x + threadIdx.x) >> 5;
    int lane = threadIdx.x & 31;
    if (warp >= NN) return;
    int t = warp;
    int b = off[t], e = off[t + 1];
    float r0 = 1.f / (nden[t * 2] + 1e-16f);
    float r1 = 1.f / (nden[t * 2 + 1] + 1e-16f);
    float4 acc0 = make_float4(0.f, 0.f, 0.f, 0.f);
    float4 acc1 = make_float4(0.f, 0.f, 0.f, 0.f);

    for (int base = b; base < e; base += 32) {
        int n = min(32, e - base);
        float w0 = 0.f, w1 = 0.f;
        int sreg = 0;
        if (lane < n) {
            sreg = csrc[base + lane];
            float2 wv = ew[base + lane];
            w0 = wv.x;
            w1 = wv.y;
        }
        for (int j = 0; j < n; j++) {
            int s = __shfl_sync(0xffffffffu, sreg, j);
            float ww0 = __shfl_sync(0xffffffffu, w0, j);
            float ww1 = __shfl_sync(0xffffffffu, w1, j);
            const float* hp = h + (long)s * C;
            if (C == 128) {
                float4 hv = *(const float4*)(hp + lane * 4);
                float w = (lane < 16) ? ww0 : ww1;
                acc0.x += hv.x * w; acc0.y += hv.y * w;
                acc0.z += hv.z * w; acc0.w += hv.w * w;
            } else {
                float4 hv0 = *(const float4*)(hp + lane * 4);
                float4 hv1 = *(const float4*)(hp + 128 + lane * 4);
                acc0.x += hv0.x * ww0; acc0.y += hv0.y * ww0;
                acc0.z += hv0.z * ww0; acc0.w += hv0.w * ww0;
                acc1.x += hv1.x * ww1; acc1.y += hv1.y * ww1;
                acc1.z += hv1.z * ww1; acc1.w += hv1.w * ww1;
            }
        }
    }
    if (C == 128) {
        float r = (lane < 16) ? r0 : r1;
        int c = lane * 4;
        const float4 bb = *(const float4*)(bias + c);
        *(float4*)(outp + (long)t * C + c) =
            make_float4(acc0.x * r + bb.x, acc0.y * r + bb.y,
                        acc0.z * r + bb.z, acc0.w * r + bb.w);
    } else {
        int c0 = lane * 4, c1 = 128 + lane * 4;
        const float4 b0 = *(const float4*)(bias + c0);
        const float4 b1 = *(const float4*)(bias + c1);
        *(float4*)(outp + (long)t * C + c0) =
            make_float4(acc0.x * r0 + b0.x, acc0.y * r0 + b0.y,
                        acc0.z * r0 + b0.z, acc0.w * r0 + b0.w);
        *(float4*)(outp + (long)t * C + c1) =
            make_float4(acc1.x * r1 + b1.x, acc1.y * r1 + b1.y,
                        acc1.z * r1 + b1.z, acc1.w * r1 + b1.w);
    }
}

// ---------------- batchnorm over N rows ----------------
__global__ void bn_stats_part(const float* __restrict__ x, float* __restrict__ gsum,
                              float* __restrict__ gsq, int rows, int C) {
    int c = threadIdx.x;  // blockDim.x == C
    float s = 0.f, sq = 0.f;
    for (int r = blockIdx.x; r < rows; r += gridDim.x) {
        float v = x[(long)r * C + c];
        s += v;
        sq += v * v;
    }
    atomicAdd(&gsum[c], s);
    atomicAdd(&gsq[c], sq);
}

__global__ void bn_finalize(const float* __restrict__ gsum, const float* __restrict__ gsq,
                            float* __restrict__ mu, float* __restrict__ rstd, int rows, int C) {
    int c = blockIdx.x * blockDim.x + threadIdx.x;
    if (c >= C) return;
    float m = gsum[c] / (float)rows;
    float var = gsq[c] / (float)rows - m * m;
    mu[c] = m;
    rstd[c] = rsqrtf(var + 1e-5f);
}

__global__ void bn_apply_relu(const float* __restrict__ in, const float* __restrict__ mu,
                              const float* __restrict__ rstd, const float* __restrict__ g,
                              const float* __restrict__ b, float* __restrict__ out,
                              long total, int C) {
    long i = (long)blockIdx.x * blockDim.x + threadIdx.x;
    if (i >= total) return;
    int c = i % C;
    float v = (in[i] - mu[c]) * rstd[c] * g[c] + b[c];
    out[i] = fmaxf(v, 0.f);
}

// ---------------- pooling (batch sorted -> contiguous ranges) ----------------
__global__ void graph_bounds(const int* __restrict__ batch, int* __restrict__ gstart) {
    int g = blockIdx.x * blockDim.x + threadIdx.x;
    if (g > GG) return;
    int lo = 0, hi = NN;
    while (lo < hi) {
        int mid = (lo + hi) >> 1;
        if (batch[mid] < g) lo = mid + 1; else hi = mid;
    }
    gstart[g] = lo;
}

__global__ void pool_sum(const float* __restrict__ x, const int* __restrict__ gstart,
                         float* __restrict__ pooled) {
    int g = blockIdx.x;
    int seg = blockIdx.y;
    int c = threadIdx.x;  // 256
    int b = gstart[g], e = gstart[g + 1];
    int len = e - b;
    int per = (len + 7) / 8;
    int rb = b + seg * per;
    int re = min(rb + per, e);
    float s = 0.f;
    for (int r = rb; r < re; r++) s += x[(long)r * 256 + c];
    atomicAdd(&pooled[g * 256 + c], s);
}

__global__ void pool_div(float* __restrict__ pooled, const int* __restrict__ gstart) {
    int i = blockIdx.x * blockDim.x + threadIdx.x;
    if (i >= GG * 256) return;
    int g = i / 256;
    float cnt = (float)(gstart[g + 1] - gstart[g]);
    pooled[i] /= fmaxf(cnt, 1.f);
}

// ---------------- FC head ----------------
__global__ void fc_kernel(const float* __restrict__ in, const float* __restrict__ W,
                          const float* __restrict__ b, float* __restrict__ out,
                          int M, int N, int K) {
    int idx = blockIdx.x * blockDim.x + threadIdx.x;
    if (idx >= M * N) return;
    int r = idx / N, c = idx % N;
    float s = b[c];
    for (int k = 0; k < K; k++) s += in[r * K + k] * W[k * N + c];
    out[idx] = s;
}

__global__ void bn_small_relu(const float* __restrict__ in, const float* __restrict__ g,
                              const float* __restrict__ b, float* __restrict__ out, int C) {
    int c = blockIdx.x * blockDim.x + threadIdx.x;
    if (c >= C) return;
    float s = 0.f, sq = 0.f;
    for (int r = 0; r < GG; r++) {
        float v = in[r * C + c];
        s += v;
        sq += v * v;
    }
    float mu = s / (float)GG;
    float rstd = rsqrtf(sq / (float)GG - mu * mu + 1e-5f);
    for (int r = 0; r < GG; r++) {
        float v = (in[r * C + c] - mu) * rstd * g[c] + b[c];
        out[r * C + c] = fmaxf(v, 0.f);
    }
}

__global__ void final_out(const float* __restrict__ z, const float* __restrict__ Wout,
                          const float* __restrict__ bout, float* __restrict__ out) {
    int g = blockIdx.x * blockDim.x + threadIdx.x;
    if (g >= GG) return;
    float s = bout[0];
    for (int k = 0; k < 256; k++) s += z[g * 256 + k] * Wout[k];
    out[g] = s;
}

// ---------------- host driver ----------------
static inline int cdiv(long a, int b) { return (int)((a + b - 1) / b); }

extern "C" void kernel_launch(void* const* d_in, const int* in_sizes, int n_in,
                              void* d_out, int out_size) {
    const float* x    = (const float*)d_in[0];
    const int*   esrc = (const int*)d_in[1];
    const int*   edst = (const int*)d_in[2];
    const int*   batch= (const int*)d_in[3];
    const float* W1   = (const float*)d_in[4];
    const float* a_s1 = (const float*)d_in[5];
    const float* a_d1 = (const float*)d_in[6];
    const float* b1   = (const float*)d_in[7];
    const float* g1   = (const float*)d_in[8];
    const float* be1  = (const float*)d_in[9];
    const float* W2   = (const float*)d_in[10];
    const float* a_s2 = (const float*)d_in[11];
    const float* a_d2 = (const float*)d_in[12];
    const float* b2   = (const float*)d_in[13];
    const float* g2   = (const float*)d_in[14];
    const float* be2  = (const float*)d_in[15];
    const float* Wf1  = (const float*)d_in[16];
    const float* bf1  = (const float*)d_in[17];
    const float* gf1  = (const float*)d_in[18];
    const float* bef1 = (const float*)d_in[19];
    const float* Wf2  = (const float*)d_in[20];
    const float* bf2  = (const float*)d_in[21];
    const float* gf2  = (const float*)d_in[22];
    const float* bef2 = (const float*)d_in[23];
    const float* Wout = (const float*)d_in[24];
    const float* bout = (const float*)d_in[25];
    float* out = (float*)d_out;

    float *h1, *y1, *x2, *h2, *y2, *x3;
    float *es1, *ed1, *es2, *ed2, *nden, *ew;
    int *deg, *off, *cursor, *csrc, *gstart;
    float *bnsum, *bnsq, *mu, *rstd, *pooled, *z1, *z1n, *z2, *z2n;
    cudaGetSymbolAddress((void**)&h1, d_h1);
    cudaGetSymbolAddress((void**)&y1, d_y1);
    cudaGetSymbolAddress((void**)&x2, d_x2);
    cudaGetSymbolAddress((void**)&h2, d_h2);
    cudaGetSymbolAddress((void**)&y2, d_y2);
    cudaGetSymbolAddress((void**)&x3, d_x3);
    cudaGetSymbolAddress((void**)&es1, d_es1);
    cudaGetSymbolAddress((void**)&ed1, d_ed1);
    cudaGetSymbolAddress((void**)&es2, d_es2);
    cudaGetSymbolAddress((void**)&ed2, d_ed2);
    cudaGetSymbolAddress((void**)&nden, d_nden);
    cudaGetSymbolAddress((void**)&ew, d_ew);
    cudaGetSymbolAddress((void**)&deg, d_deg);
    cudaGetSymbolAddress((void**)&off, d_off);
    cudaGetSymbolAddress((void**)&cursor, d_cursor);
    cudaGetSymbolAddress((void**)&csrc, d_csrc);
    cudaGetSymbolAddress((void**)&gstart, d_gstart);
    cudaGetSymbolAddress((void**)&bnsum, d_bnsum);
    cudaGetSymbolAddress((void**)&bnsq, d_bnsq);
    cudaGetSymbolAddress((void**)&mu, d_mu);
    cudaGetSymbolAddress((void**)&rstd, d_rstd);
    cudaGetSymbolAddress((void**)&pooled, d_pooled);
    cudaGetSymbolAddress((void**)&z1, d_z1);
    cudaGetSymbolAddress((void**)&z1n, d_z1n);
    cudaGetSymbolAddress((void**)&z2, d_z2);
    cudaGetSymbolAddress((void**)&z2n, d_z2n);

    const int TB = 256;

    // launches 1-3: CSR prep (small)
    fill_int<<<cdiv(NN, TB), TB>>>(deg, NN, 1);   // self-loop counts as 1
    count_deg<<<cdiv(EE, TB), TB>>>(edst, deg);
    scan_offsets<<<1, 1024>>>(deg, off, cursor);
    // launch 4: GEMM layer 1 (ncu profile position)
    gemm_tf32<<<dim3(128 / 64, cdiv(NN, 128)), 256>>>(x, W1, h1, NN, 128, 64);
    // CSR fill + pooling bounds
    csr_fill_edges<<<cdiv(EE, TB), TB>>>(esrc, edst, cursor, csrc);
    csr_fill_loops<<<cdiv(NN, TB), TB>>>(cursor, csrc);
    graph_bounds<<<1, 256>>>(batch, gstart);

    // ===== layer 1 =====
    fillf<<<1, 256>>>(bnsum, 256, 0.f);
    fillf<<<1, 256>>>(bnsq, 256, 0.f);
    attn_coef<<<cdiv(NN * 2, TB), TB>>>(h1, a_s1, a_d1, es1, ed1, 64);
    node_stats<<<cdiv(NN * 32, TB), TB>>>(off, csrc, es1, ed1, nden, (float2*)ew);
    node_aggregate<128><<<cdiv(NN * 32, TB), TB>>>(off, csrc, (float2*)ew, nden, h1, b1, y1);
    bn_stats_part<<<512, 128>>>(y1, bnsum, bnsq, NN, 128);
    bn_finalize<<<1, 128>>>(bnsum, bnsq, mu, rstd, NN, 128);
    bn_apply_relu<<<cdiv((long)NN * 128, TB), TB>>>(y1, mu, rstd, g1, be1, x2, (long)NN * 128, 128);

    // ===== layer 2 =====
    fillf<<<1, 256>>>(bnsum, 256, 0.f);
    fillf<<<1, 256>>>(bnsq, 256, 0.f);
    gemm_tf32<<<dim3(256 / 64, cdiv(NN, 128)), 256>>>(x2, W2, h2, NN, 256, 128);
    attn_coef<<<cdiv(NN * 2, TB), TB>>>(h2, a_s2, a_d2, es2, ed2, 128);
    node_stats<<<cdiv(NN * 32, TB), TB>>>(off, csrc, es2, ed2, nden, (float2*)ew);
    node_aggregate<256><<<cdiv(NN * 32, TB), TB>>>(off, csrc, (float2*)ew, nden, h2, b2, y2);
    bn_stats_part<<<512, 256>>>(y2, bnsum, bnsq, NN, 256);
    bn_finalize<<<1, 256>>>(bnsum, bnsq, mu, rstd, NN, 256);
    bn_apply_relu<<<cdiv((long)NN * 256, TB), TB>>>(y2, mu, rstd, g2, be2, x3, (long)NN * 256, 256);

    // ===== pooling =====
    fillf<<<cdiv(GG * 256, TB), TB>>>(pooled, GG * 256, 0.f);
    pool_sum<<<dim3(GG, 8), 256>>>(x3, gstart, pooled);
    pool_div<<<cdiv(GG * 256, TB), TB>>>(pooled, gstart);

    // ===== FC head =====
    fc_kernel<<<cdiv(GG * 512, TB), TB>>>(pooled, Wf1, bf1, z1, GG, 512, 256);
    bn_small_relu<<<2, 256>>>(z1, gf1, bef1, z1n, 512);
    fc_kernel<<<cdiv(GG * 256, TB), TB>>>(z1n, Wf2, bf2, z2, GG, 256, 512);
    bn_small_relu<<<1, 256>>>(z2, gf2, bef2, z2n, 256);
    final_out<<<1, GG>>>(z2n, Wout, bout, out);
}

// round 5
// speedup vs baseline: 2.3923x; 1.1717x over previous
#include <cuda_runtime.h>
#include <cuda_bf16.h>

// Problem constants (fixed by the reference)
#define NN 50000
#define EE 500000
#define HH 2
#define GG 128

// ---------------- scratch (static __device__ globals; no runtime alloc) ----------------
__device__ float d_h1[NN * 128];     // layer1 linear out
__device__ float d_y1[NN * 128];     // layer1 GAT out (post bias, pre-BN)
__device__ float d_h2[NN * 256];     // layer2 linear out
__device__ float d_y2[NN * 256];     // layer2 GAT out (post bias, pre-BN)
__device__ float d_es1[NN * 2], d_ed1[NN * 2];
__device__ float d_es2[NN * 2], d_ed2[NN * 2];
__device__ float d_nden[NN * 2];
__device__ float d_ew[(EE + NN) * 2];   // per-edge unnormalized softmax weights (CSR order)
__device__ int   d_deg[NN], d_off[NN + 1], d_cursor[NN];
__device__ int   d_csrc[EE + NN];
__device__ int   d_gstart[GG + 1];
__device__ float d_bs1[128], d_bq1[128], d_scale1[128], d_shift1[128];
__device__ float d_bs2[256], d_bq2[256], d_scale2[256], d_shift2[256];
__device__ float d_pooled[GG * 256];
__device__ float d_z1[GG * 512], d_z1n[GG * 512];
__device__ float d_z2[GG * 256], d_z2n[GG * 256];

// ---------------- fills ----------------
__global__ void zero_all(float* es1, float* ed1, float* es2, float* ed2,
                         float* bs1, float* bq1, float* bs2, float* bq2) {
    int i = blockIdx.x * blockDim.x + threadIdx.x;
    if (i < NN * 2) { es1[i] = 0.f; ed1[i] = 0.f; es2[i] = 0.f; ed2[i] = 0.f; }
    if (i < 128) { bs1[i] = 0.f; bq1[i] = 0.f; }
    if (i < 256) { bs2[i] = 0.f; bq2[i] = 0.f; }
}
__global__ void fillf(float* p, long n, float v) {
    long i = (long)blockIdx.x * blockDim.x + threadIdx.x;
    if (i < n) p[i] = v;
}
__global__ void fill_int(int* p, int n, int v) {
    int i = blockIdx.x * blockDim.x + threadIdx.x;
    if (i < n) p[i] = v;
}

// ---------------- CSR build ----------------
__global__ void count_deg(const int* __restrict__ dst, int* __restrict__ deg) {
    int e = blockIdx.x * blockDim.x + threadIdx.x;
    if (e < EE) atomicAdd(&deg[dst[e]], 1);
}

__global__ void scan_offsets(const int* __restrict__ deg, int* __restrict__ off,
                             int* __restrict__ cursor) {
    __shared__ int part[1024];
    const int CH = (NN + 1023) / 1024;
    int t = threadIdx.x;
    int base = t * CH;
    int s = 0;
    for (int i = 0; i < CH; i++) {
        int idx = base + i;
        if (idx < NN) s += deg[idx];
    }
    part[t] = s;
    __syncthreads();
    for (int d = 1; d < 1024; d <<= 1) {
        int v = (t >= d) ? part[t - d] : 0;
        __syncthreads();
        part[t] += v;
        __syncthreads();
    }
    int run = (t == 0) ? 0 : part[t - 1];
    for (int i = 0; i < CH; i++) {
        int idx = base + i;
        if (idx < NN) {
            off[idx] = run;
            cursor[idx] = run;
            run += deg[idx];
        }
    }
    if (t == 1023) off[NN] = part[1023];
}

__global__ void csr_fill_edges(const int* __restrict__ src, const int* __restrict__ dst,
                               int* __restrict__ cursor, int* __restrict__ csrc) {
    int e = blockIdx.x * blockDim.x + threadIdx.x;
    if (e >= EE) return;
    int t = dst[e];
    int p = atomicAdd(&cursor[t], 1);
    csrc[p] = src[e];
}
__global__ void csr_fill_loops(int* __restrict__ cursor, int* __restrict__ csrc) {
    int n = blockIdx.x * blockDim.x + threadIdx.x;
    if (n >= NN) return;
    int p = atomicAdd(&cursor[n], 1);
    csrc[p] = n;
}

// ---------------- tf32 tensor-core GEMM with fused epilogues ----------------
// C[M,N] = A'[M,K] @ B[K,N];  A' = APPLY_BN ? relu(A*scale+shift) : A
// Epilogue also accumulates es[row,head] += sum_col C*asrc[col] (and ed), where
// head = (2*bcol >= N) — each 64-col block lies entirely in one head.
__device__ __forceinline__ unsigned f2tf(float f) {
    unsigned r;
    asm("cvt.rna.tf32.f32 %0, %1;" : "=r"(r) : "f"(f));
    return r;
}
__device__ __forceinline__ void mma_tf32(float4& c, const unsigned* a, const unsigned* b) {
    asm volatile(
        "mma.sync.aligned.m16n8k8.row.col.f32.tf32.tf32.f32 "
        "{%0,%1,%2,%3}, {%4,%5,%6,%7}, {%8,%9}, {%0,%1,%2,%3};"
        : "+f"(c.x), "+f"(c.y), "+f"(c.z), "+f"(c.w)
        : "r"(a[0]), "r"(a[1]), "r"(a[2]), "r"(a[3]), "r"(b[0]), "r"(b[1]));
}

template <bool APPLY_BN>
__global__ void gemm_tf32(const float* __restrict__ A, const float* __restrict__ B,
                          float* __restrict__ C, int M, int N, int K,
                          const float* __restrict__ scale, const float* __restrict__ shift,
                          const float* __restrict__ asrc, const float* __restrict__ adst,
                          float* __restrict__ es, float* __restrict__ ed) {
    __shared__ unsigned As[128][17];
    __shared__ unsigned Bs[16][72];
    const int brow = blockIdx.y * 128;
    const int bcol = blockIdx.x * 64;
    const int tid = threadIdx.x;
    const int w = tid >> 5, l = tid & 31;
    const int wm = w & 3, wn = w >> 2;
    const int mbase = wm * 32, nbase = wn * 32;
    const int g = l >> 2, tg = l & 3;
    float4 acc[2][4];
    #pragma unroll
    for (int i = 0; i < 2; i++)
        #pragma unroll
        for (int j = 0; j < 4; j++) acc[i][j] = make_float4(0.f, 0.f, 0.f, 0.f);

    for (int k0 = 0; k0 < K; k0 += 16) {
        #pragma unroll
        for (int i = tid; i < 512; i += 256) {
            int r = i >> 2, c4 = (i & 3) * 4;
            int gr = brow + r;
            float4 v = make_float4(0.f, 0.f, 0.f, 0.f);
            if (gr < M) {
                v = *(const float4*)(A + (long)gr * K + k0 + c4);
                if (APPLY_BN) {
                    int c = k0 + c4;
                    v.x = fmaxf(fmaf(v.x, __ldg(scale + c + 0), __ldg(shift + c + 0)), 0.f);
                    v.y = fmaxf(fmaf(v.y, __ldg(scale + c + 1), __ldg(shift + c + 1)), 0.f);
                    v.z = fmaxf(fmaf(v.z, __ldg(scale + c + 2), __ldg(shift + c + 2)), 0.f);
                    v.w = fmaxf(fmaf(v.w, __ldg(scale + c + 3), __ldg(shift + c + 3)), 0.f);
                }
            }
            As[r][c4 + 0] = f2tf(v.x);
            As[r][c4 + 1] = f2tf(v.y);
            As[r][c4 + 2] = f2tf(v.z);
            As[r][c4 + 3] = f2tf(v.w);
        }
        {
            int r = tid >> 4, c4 = (tid & 15) * 4;
            float4 v = *(const float4*)(B + (long)(k0 + r) * N + bcol + c4);
            Bs[r][c4 + 0] = f2tf(v.x);
            Bs[r][c4 + 1] = f2tf(v.y);
            Bs[r][c4 + 2] = f2tf(v.z);
            Bs[r][c4 + 3] = f2tf(v.w);
        }
        __syncthreads();
        #pragma unroll
        for (int k8 = 0; k8 < 16; k8 += 8) {
            unsigned af[2][4], bf[4][2];
            #pragma unroll
            for (int mt = 0; mt < 2; mt++) {
                int r0 = mbase + mt * 16 + g;
                int c = k8 + tg;
                af[mt][0] = As[r0][c];
                af[mt][1] = As[r0 + 8][c];
                af[mt][2] = As[r0][c + 4];
                af[mt][3] = As[r0 + 8][c + 4];
            }
            #pragma unroll
            for (int nt = 0; nt < 4; nt++) {
                int cb = nbase + nt * 8 + g;
                int rb = k8 + tg;
                bf[nt][0] = Bs[rb][cb];
                bf[nt][1] = Bs[rb + 4][cb];
            }
            #pragma unroll
            for (int mt = 0; mt < 2; mt++)
                #pragma unroll
                for (int nt = 0; nt < 4; nt++) mma_tf32(acc[mt][nt], af[mt], bf[nt]);
        }
        __syncthreads();
    }

    // store C
    #pragma unroll
    for (int mt = 0; mt < 2; mt++) {
        #pragma unroll
        for (int nt = 0; nt < 4; nt++) {
            int row = brow + mbase + mt * 16 + g;
            int col = bcol + nbase + nt * 8 + 2 * tg;
            if (row < M)
                *(float2*)(C + (long)row * N + col) = make_float2(acc[mt][nt].x, acc[mt][nt].y);
            if (row + 8 < M)
                *(float2*)(C + (long)(row + 8) * N + col) = make_float2(acc[mt][nt].z, acc[mt][nt].w);
        }
    }

    // fused attention-logit epilogue
    {
        int head = (2 * bcol >= N) ? 1 : 0;
        float av_s[8], av_d[8];
        #pragma unroll
        for (int nt = 0; nt < 4; nt++) {
            int col = bcol + nbase + nt * 8 + 2 * tg;
            av_s[nt * 2 + 0] = __ldg(asrc + col);
            av_s[nt * 2 + 1] = __ldg(asrc + col + 1);
            av_d[nt * 2 + 0] = __ldg(adst + col);
            av_d[nt * 2 + 1] = __ldg(adst + col + 1);
        }
        #pragma unroll
        for (int mt = 0; mt < 2; mt++) {
            float pes0 = 0.f, ped0 = 0.f, pes8 = 0.f, ped8 = 0.f;
            #pragma unroll
            for (int nt = 0; nt < 4; nt++) {
                float4 a = acc[mt][nt];
                pes0 += a.x * av_s[nt * 2] + a.y * av_s[nt * 2 + 1];
                ped0 += a.x * av_d[nt * 2] + a.y * av_d[nt * 2 + 1];
                pes8 += a.z * av_s[nt * 2] + a.w * av_s[nt * 2 + 1];
                ped8 += a.z * av_d[nt * 2] + a.w * av_d[nt * 2 + 1];
            }
            // reduce over tg (quad lanes)
            #pragma unroll
            for (int o = 1; o <= 2; o <<= 1) {
                pes0 += __shfl_xor_sync(0xffffffffu, pes0, o);
                ped0 += __shfl_xor_sync(0xffffffffu, ped0, o);
                pes8 += __shfl_xor_sync(0xffffffffu, pes8, o);
                ped8 += __shfl_xor_sync(0xffffffffu, ped8, o);
            }
            if (tg == 0) {
                int row = brow + mbase + mt * 16 + g;
                if (row < M) {
                    atomicAdd(&es[row * 2 + head], pes0);
                    atomicAdd(&ed[row * 2 + head], ped0);
                }
                if (row + 8 < M) {
                    atomicAdd(&es[(row + 8) * 2 + head], pes8);
                    atomicAdd(&ed[(row + 8) * 2 + head], ped8);
                }
            }
        }
    }
}

// ---------------- softmax stats: per-node max+denom, write per-edge weights ----------------
__global__ void node_stats(const int* __restrict__ off, const int* __restrict__ csrc,
                           const float* __restrict__ es, const float* __restrict__ ed,
                           float* __restrict__ nden, float2* __restrict__ ew) {
    int warp = (blockIdx.x * blockDim.x + threadIdx.x) >> 5;
    int lane = threadIdx.x & 31;
    if (warp >= NN) return;
    int t = warp;
    int b = off[t], e = off[t + 1];
    float ed0 = ed[t * 2], ed1 = ed[t * 2 + 1];
    float m0 = -1e30f, m1 = -1e30f;
    for (int i = b + lane; i < e; i += 32) {
        int s = csrc[i];
        float2 esv = *(const float2*)(es + s * 2);
        float v0 = esv.x + ed0; v0 = v0 > 0.f ? v0 : 0.2f * v0;
        float v1 = esv.y + ed1; v1 = v1 > 0.f ? v1 : 0.2f * v1;
        m0 = fmaxf(m0, v0);
        m1 = fmaxf(m1, v1);
    }
    #pragma unroll
    for (int o = 16; o; o >>= 1) {
        m0 = fmaxf(m0, __shfl_xor_sync(0xffffffffu, m0, o));
        m1 = fmaxf(m1, __shfl_xor_sync(0xffffffffu, m1, o));
    }
    float s0 = 0.f, s1 = 0.f;
    for (int i = b + lane; i < e; i += 32) {
        int s = csrc[i];
        float2 esv = *(const float2*)(es + s * 2);
        float v0 = esv.x + ed0; v0 = v0 > 0.f ? v0 : 0.2f * v0;
        float v1 = esv.y + ed1; v1 = v1 > 0.f ? v1 : 0.2f * v1;
        float w0 = __expf(v0 - m0);
        float w1 = __expf(v1 - m1);
        ew[i] = make_float2(w0, w1);
        s0 += w0;
        s1 += w1;
    }
    #pragma unroll
    for (int o = 16; o; o >>= 1) {
        s0 += __shfl_xor_sync(0xffffffffu, s0, o);
        s1 += __shfl_xor_sync(0xffffffffu, s1, o);
    }
    if (lane == 0) {
        nden[t * 2] = s0;
        nden[t * 2 + 1] = s1;
    }
}

// ---------------- gather aggregation + fused BN stats; 1024-thread blocks ----------------
template <int C>
__global__ void node_aggregate(const int* __restrict__ off, const int* __restrict__ csrc,
                               const float2* __restrict__ ew, const float* __restrict__ nden,
                               const float* __restrict__ h, const float* __restrict__ bias,
                               float* __restrict__ outp,
                               float* __restrict__ bnsum, float* __restrict__ bnsq) {
    __shared__ float ssum[C];
    __shared__ float ssq[C];
    const int tid = threadIdx.x;
    for (int i = tid; i < C; i += 1024) { ssum[i] = 0.f; ssq[i] = 0.f; }
    __syncthreads();

    int t = blockIdx.x * 32 + (tid >> 5);
    int lane = tid & 31;
    bool valid = t < NN;
    int b = 0, e = 0;
    float r0 = 0.f, r1 = 0.f;
    if (valid) {
        b = off[t];
        e = off[t + 1];
        r0 = 1.f / (nden[t * 2] + 1e-16f);
        r1 = 1.f / (nden[t * 2 + 1] + 1e-16f);
    }
    float4 acc0 = make_float4(0.f, 0.f, 0.f, 0.f);
    float4 acc1 = make_float4(0.f, 0.f, 0.f, 0.f);

    for (int base = b; base < e; base += 32) {
        int n = min(32, e - base);
        float w0 = 0.f, w1 = 0.f;
        int sreg = 0;
        if (lane < n) {
            sreg = csrc[base + lane];
            float2 wv = ew[base + lane];
            w0 = wv.x;
            w1 = wv.y;
        }
        for (int j = 0; j < n; j++) {
            int s = __shfl_sync(0xffffffffu, sreg, j);
            float ww0 = __shfl_sync(0xffffffffu, w0, j);
            float ww1 = __shfl_sync(0xffffffffu, w1, j);
            const float* hp = h + (long)s * C;
            if (C == 128) {
                float4 hv = *(const float4*)(hp + lane * 4);
                float w = (lane < 16) ? ww0 : ww1;
                acc0.x += hv.x * w; acc0.y += hv.y * w;
                acc0.z += hv.z * w; acc0.w += hv.w * w;
            } else {
                float4 hv0 = *(const float4*)(hp + lane * 4);
                float4 hv1 = *(const float4*)(hp + 128 + lane * 4);
                acc0.x += hv0.x * ww0; acc0.y += hv0.y * ww0;
                acc0.z += hv0.z * ww0; acc0.w += hv0.w * ww0;
                acc1.x += hv1.x * ww1; acc1.y += hv1.y * ww1;
                acc1.z += hv1.z * ww1; acc1.w += hv1.w * ww1;
            }
        }
    }

    if (valid) {
        if (C == 128) {
            float r = (lane < 16) ? r0 : r1;
            int c = lane * 4;
            const float4 bb = *(const float4*)(bias + c);
            float4 o = make_float4(acc0.x * r + bb.x, acc0.y * r + bb.y,
                                   acc0.z * r + bb.z, acc0.w * r + bb.w);
            *(float4*)(outp + (long)t * C + c) = o;
            atomicAdd(&ssum[c + 0], o.x); atomicAdd(&ssq[c + 0], o.x * o.x);
            atomicAdd(&ssum[c + 1], o.y); atomicAdd(&ssq[c + 1], o.y * o.y);
            atomicAdd(&ssum[c + 2], o.z); atomicAdd(&ssq[c + 2], o.z * o.z);
            atomicAdd(&ssum[c + 3], o.w); atomicAdd(&ssq[c + 3], o.w * o.w);
        } else {
            int c0 = lane * 4, c1 = 128 + lane * 4;
            const float4 b0 = *(const float4*)(bias + c0);
            const float4 b1 = *(const float4*)(bias + c1);
            float4 o0 = make_float4(acc0.x * r0 + b0.x, acc0.y * r0 + b0.y,
                                    acc0.z * r0 + b0.z, acc0.w * r0 + b0.w);
            float4 o1 = make_float4(acc1.x * r1 + b1.x, acc1.y * r1 + b1.y,
                                    acc1.z * r1 + b1.z, acc1.w * r1 + b1.w);
            *(float4*)(outp + (long)t * C + c0) = o0;
            *(float4*)(outp + (long)t * C + c1) = o1;
            atomicAdd(&ssum[c0 + 0], o0.x); atomicAdd(&ssq[c0 + 0], o0.x * o0.x);
            atomicAdd(&ssum[c0 + 1], o0.y); atomicAdd(&ssq[c0 + 1], o0.y * o0.y);
            atomicAdd(&ssum[c0 + 2], o0.z); atomicAdd(&ssq[c0 + 2], o0.z * o0.z);
            atomicAdd(&ssum[c0 + 3], o0.w); atomicAdd(&ssq[c0 + 3], o0.w * o0.w);
            atomicAdd(&ssum[c1 + 0], o1.x); atomicAdd(&ssq[c1 + 0], o1.x * o1.x);
            atomicAdd(&ssum[c1 + 1], o1.y); atomicAdd(&ssq[c1 + 1], o1.y * o1.y);
            atomicAdd(&ssum[c1 + 2], o1.z); atomicAdd(&ssq[c1 + 2], o1.z * o1.z);
            atomicAdd(&ssum[c1 + 3], o1.w); atomicAdd(&ssq[c1 + 3], o1.w * o1.w);
        }
    }
    __syncthreads();
    for (int i = tid; i < C; i += 1024) {
        atomicAdd(&bnsum[i], ssum[i]);
        atomicAdd(&bnsq[i], ssq[i]);
    }
}

// ---------------- BN finalize: write fused scale/shift ----------------
__global__ void bn_finalize(const float* __restrict__ gsum, const float* __restrict__ gsq,
                            const float* __restrict__ gamma, const float* __restrict__ beta,
                            float* __restrict__ scale, float* __restrict__ shift,
                            int rows, int C) {
    int c = blockIdx.x * blockDim.x + threadIdx.x;
    if (c >= C) return;
    float m = gsum[c] / (float)rows;
    float var = gsq[c] / (float)rows - m * m;
    float rstd = rsqrtf(var + 1e-5f);
    float sc = rstd * gamma[c];
    scale[c] = sc;
    shift[c] = beta[c] - m * sc;
}

// ---------------- pooling (batch sorted -> contiguous ranges), BN2+relu fused ----------------
__global__ void graph_bounds(const int* __restrict__ batch, int* __restrict__ gstart) {
    int g = blockIdx.x * blockDim.x + threadIdx.x;
    if (g > GG) return;
    int lo = 0, hi = NN;
    while (lo < hi) {
        int mid = (lo + hi) >> 1;
        if (batch[mid] < g) lo = mid + 1; else hi = mid;
    }
    gstart[g] = lo;
}

__global__ void pool_sum(const float* __restrict__ y, const int* __restrict__ gstart,
                         const float* __restrict__ scale, const float* __restrict__ shift,
                         float* __restrict__ pooled) {
    int g = blockIdx.x;
    int seg = blockIdx.y;
    int c = threadIdx.x;  // 256
    float sc = scale[c], sh = shift[c];
    int b = gstart[g], e = gstart[g + 1];
    int len = e - b;
    int per = (len + 7) / 8;
    int rb = b + seg * per;
    int re = min(rb + per, e);
    float s = 0.f;
    for (int r = rb; r < re; r++) s += fmaxf(fmaf(y[(long)r * 256 + c], sc, sh), 0.f);
    atomicAdd(&pooled[g * 256 + c], s);
}

__global__ void pool_div(float* __restrict__ pooled, const int* __restrict__ gstart) {
    int i = blockIdx.x * blockDim.x + threadIdx.x;
    if (i >= GG * 256) return;
    int g = i / 256;
    float cnt = (float)(gstart[g + 1] - gstart[g]);
    pooled[i] /= fmaxf(cnt, 1.f);
}

// ---------------- FC head ----------------
__global__ void fc_kernel(const float* __restrict__ in, const float* __restrict__ W,
                          const float* __restrict__ b, float* __restrict__ out,
                          int M, int N, int K) {
    int idx = blockIdx.x * blockDim.x + threadIdx.x;
    if (idx >= M * N) return;
    int r = idx / N, c = idx % N;
    float s = b[c];
    for (int k = 0; k < K; k++) s += in[r * K + k] * W[k * N + c];
    out[idx] = s;
}

__global__ void bn_small_relu(const float* __restrict__ in, const float* __restrict__ g,
                              const float* __restrict__ b, float* __restrict__ out, int C) {
    int c = blockIdx.x * blockDim.x + threadIdx.x;
    if (c >= C) return;
    float s = 0.f, sq = 0.f;
    for (int r = 0; r < GG; r++) {
        float v = in[r * C + c];
        s += v;
        sq += v * v;
    }
    float mu = s / (float)GG;
    float rstd = rsqrtf(sq / (float)GG - mu * mu + 1e-5f);
    for (int r = 0; r < GG; r++) {
        float v = (in[r * C + c] - mu) * rstd * g[c] + b[c];
        out[r * C + c] = fmaxf(v, 0.f);
    }
}

__global__ void final_out(const float* __restrict__ z, const float* __restrict__ Wout,
                          const float* __restrict__ bout, float* __restrict__ out) {
    int g = blockIdx.x * blockDim.x + threadIdx.x;
    if (g >= GG) return;
    float s = bout[0];
    for (int k = 0; k < 256; k++) s += z[g * 256 + k] * Wout[k];
    out[g] = s;
}

// ---------------- host driver ----------------
static inline int cdiv(long a, int b) { return (int)((a + b - 1) / b); }

extern "C" void kernel_launch(void* const* d_in, const int* in_sizes, int n_in,
                              void* d_out, int out_size) {
    const float* x    = (const float*)d_in[0];
    const int*   esrc = (const int*)d_in[1];
    const int*   edst = (const int*)d_in[2];
    const int*   batch= (const int*)d_in[3];
    const float* W1   = (const float*)d_in[4];
    const float* a_s1 = (const float*)d_in[5];
    const float* a_d1 = (const float*)d_in[6];
    const float* b1   = (const float*)d_in[7];
    const float* g1   = (const float*)d_in[8];
    const float* be1  = (const float*)d_in[9];
    const float* W2   = (const float*)d_in[10];
    const float* a_s2 = (const float*)d_in[11];
    const float* a_d2 = (const float*)d_in[12];
    const float* b2   = (const float*)d_in[13];
    const float* g2   = (const float*)d_in[14];
    const float* be2  = (const float*)d_in[15];
    const float* Wf1  = (const float*)d_in[16];
    const float* bf1  = (const float*)d_in[17];
    const float* gf1  = (const float*)d_in[18];
    const float* bef1 = (const float*)d_in[19];
    const float* Wf2  = (const float*)d_in[20];
    const float* bf2  = (const float*)d_in[21];
    const float* gf2  = (const float*)d_in[22];
    const float* bef2 = (const float*)d_in[23];
    const float* Wout = (const float*)d_in[24];
    const float* bout = (const float*)d_in[25];
    float* out = (float*)d_out;

    float *h1, *y1, *h2, *y2;
    float *es1, *ed1, *es2, *ed2, *nden, *ew;
    int *deg, *off, *cursor, *csrc, *gstart;
    float *bs1, *bq1, *sc1, *sh1, *bs2, *bq2, *sc2, *sh2;
    float *pooled, *z1, *z1n, *z2, *z2n;
    cudaGetSymbolAddress((void**)&h1, d_h1);
    cudaGetSymbolAddress((void**)&y1, d_y1);
    cudaGetSymbolAddress((void**)&h2, d_h2);
    cudaGetSymbolAddress((void**)&y2, d_y2);
    cudaGetSymbolAddress((void**)&es1, d_es1);
    cudaGetSymbolAddress((void**)&ed1, d_ed1);
    cudaGetSymbolAddress((void**)&es2, d_es2);
    cudaGetSymbolAddress((void**)&ed2, d_ed2);
    cudaGetSymbolAddress((void**)&nden, d_nden);
    cudaGetSymbolAddress((void**)&ew, d_ew);
    cudaGetSymbolAddress((void**)&deg, d_deg);
    cudaGetSymbolAddress((void**)&off, d_off);
    cudaGetSymbolAddress((void**)&cursor, d_cursor);
    cudaGetSymbolAddress((void**)&csrc, d_csrc);
    cudaGetSymbolAddress((void**)&gstart, d_gstart);
    cudaGetSymbolAddress((void**)&bs1, d_bs1);
    cudaGetSymbolAddress((void**)&bq1, d_bq1);
    cudaGetSymbolAddress((void**)&sc1, d_scale1);
    cudaGetSymbolAddress((void**)&sh1, d_shift1);
    cudaGetSymbolAddress((void**)&bs2, d_bs2);
    cudaGetSymbolAddress((void**)&bq2, d_bq2);
    cudaGetSymbolAddress((void**)&sc2, d_scale2);
    cudaGetSymbolAddress((void**)&sh2, d_shift2);
    cudaGetSymbolAddress((void**)&pooled, d_pooled);
    cudaGetSymbolAddress((void**)&z1, d_z1);
    cudaGetSymbolAddress((void**)&z1n, d_z1n);
    cudaGetSymbolAddress((void**)&z2, d_z2);
    cudaGetSymbolAddress((void**)&z2n, d_z2n);

    const int TB = 256;

    // 1-3: zero + degree count
    zero_all<<<cdiv(NN * 2, TB), TB>>>(es1, ed1, es2, ed2, bs1, bq1, bs2, bq2);
    fill_int<<<cdiv(NN, TB), TB>>>(deg, NN, 1);   // self-loop counts as 1
    count_deg<<<cdiv(EE, TB), TB>>>(edst, deg);
    // 4: GEMM layer 1 (+es1/ed1 fused) — ncu window
    gemm_tf32<false><<<dim3(2, cdiv(NN, 128)), 256>>>(x, W1, h1, NN, 128, 64,
                                                      nullptr, nullptr, a_s1, a_d1, es1, ed1);
    // CSR finish + graph bounds
    scan_offsets<<<1, 1024>>>(deg, off, cursor);
    csr_fill_edges<<<cdiv(EE, TB), TB>>>(esrc, edst, cursor, csrc);
    csr_fill_loops<<<cdiv(NN, TB), TB>>>(cursor, csrc);
    graph_bounds<<<1, 256>>>(batch, gstart);

    // ===== layer 1 =====
    node_stats<<<cdiv(NN * 32, TB), TB>>>(off, csrc, es1, ed1, nden, (float2*)ew);
    node_aggregate<128><<<cdiv(NN, 32), 1024>>>(off, csrc, (float2*)ew, nden, h1, b1, y1, bs1, bq1);
    bn_finalize<<<1, 128>>>(bs1, bq1, g1, be1, sc1, sh1, NN, 128);

    // ===== layer 2 (BN1+relu fused into A-load) =====
    gemm_tf32<true><<<dim3(4, cdiv(NN, 128)), 256>>>(y1, W2, h2, NN, 256, 128,
                                                     sc1, sh1, a_s2, a_d2, es2, ed2);
    node_stats<<<cdiv(NN * 32, TB), TB>>>(off, csrc, es2, ed2, nden, (float2*)ew);
    node_aggregate<256><<<cdiv(NN, 32), 1024>>>(off, csrc, (float2*)ew, nden, h2, b2, y2, bs2, bq2);
    bn_finalize<<<1, 256>>>(bs2, bq2, g2, be2, sc2, sh2, NN, 256);

    // ===== pooling (BN2+relu fused) =====
    fillf<<<cdiv(GG * 256, TB), TB>>>(pooled, GG * 256, 0.f);
    pool_sum<<<dim3(GG, 8), 256>>>(y2, gstart, sc2, sh2, pooled);
    pool_div<<<cdiv(GG * 256, TB), TB>>>(pooled, gstart);

    // ===== FC head =====
    fc_kernel<<<cdiv(GG * 512, TB), TB>>>(pooled, Wf1, bf1, z1, GG, 512, 256);
    bn_small_relu<<<2, 256>>>(z1, gf1, bef1, z1n, 512);
    fc_kernel<<<cdiv(GG * 256, TB), TB>>>(z1n, Wf2, bf2, z2, GG, 256, 512);
    bn_small_relu<<<1, 256>>>(z2, gf2, bef2, z2n, 256);
    final_out<<<1, GG>>>(z2n, Wout, bout, out);
}

// round 7
// speedup vs baseline: 2.5597x; 1.0700x over previous
#include <cuda_runtime.h>
#include <cuda_bf16.h>

#define NN 50000
#define EE 500000
#define HH 2
#define GG 128

// ---------------- scratch ----------------
__device__ float d_h1[NN * 128];
__device__ float d_y1[NN * 128];
__device__ float d_h2[NN * 256];
__device__ float d_y2[NN * 256];
__device__ float d_es1[NN * 2], d_ed1[NN * 2];
__device__ float d_es2[NN * 2], d_ed2[NN * 2];
__device__ int   d_deg[NN], d_off[NN + 1], d_cursor[NN];
__device__ int   d_csrc[EE + NN];
__device__ int   d_gstart[GG + 1];
__device__ float d_bs1[128], d_bq1[128];
__device__ float d_bs2[256], d_bq2[256];
__device__ float d_pooled[GG * 256];
__device__ float d_z1[GG * 512], d_z1n[GG * 512];
__device__ float d_z2[GG * 256], d_z2n[GG * 256];

static const int GEMM1_BLOCKS = 2 * ((NN + 127) / 128);            // 782
static const int CSR_BLOCKS = (EE + NN + 255) / 256;               // 2149

// ---------------- CSR: degree count (deg starts zeroed; re-zeroed at graph tail) ----------------
__global__ void count_deg(const int* __restrict__ dst, int* __restrict__ deg) {
    int e = blockIdx.x * blockDim.x + threadIdx.x;
    if (e < EE) atomicAdd(&deg[dst[e]], 1);
}

// single-block scan; degree = deg[i] + 1 (implicit self-loop)
__global__ void scan_offsets(const int* __restrict__ deg, int* __restrict__ off,
                             int* __restrict__ cursor) {
    __shared__ int part[1024];
    const int CH = (NN + 1023) / 1024;
    int t = threadIdx.x;
    int base = t * CH;
    int s = 0;
    for (int i = 0; i < CH; i++) {
        int idx = base + i;
        if (idx < NN) s += deg[idx] + 1;
    }
    part[t] = s;
    __syncthreads();
    for (int d = 1; d < 1024; d <<= 1) {
        int v = (t >= d) ? part[t - d] : 0;
        __syncthreads();
        part[t] += v;
        __syncthreads();
    }
    int run = (t == 0) ? 0 : part[t - 1];
    for (int i = 0; i < CH; i++) {
        int idx = base + i;
        if (idx < NN) {
            off[idx] = run;
            cursor[idx] = run;
            run += deg[idx] + 1;
        }
    }
    if (t == 1023) off[NN] = part[1023];
}

// ---------------- tf32 GEMM body (device fn, called from combo1 and gemm_k) ----------------
__device__ __forceinline__ unsigned f2tf(float f) {
    unsigned r;
    asm("cvt.rna.tf32.f32 %0, %1;" : "=r"(r) : "f"(f));
    return r;
}
__device__ __forceinline__ void mma_tf32(float4& c, const unsigned* a, const unsigned* b) {
    asm volatile(
        "mma.sync.aligned.m16n8k8.row.col.f32.tf32.tf32.f32 "
        "{%0,%1,%2,%3}, {%4,%5,%6,%7}, {%8,%9}, {%0,%1,%2,%3};"
        : "+f"(c.x), "+f"(c.y), "+f"(c.z), "+f"(c.w)
        : "r"(a[0]), "r"(a[1]), "r"(a[2]), "r"(a[3]), "r"(b[0]), "r"(b[1]));
}

template <bool APPLY_BN>
__device__ void gemm_body(int bx, int by,
                          const float* __restrict__ A, const float* __restrict__ B,
                          float* __restrict__ C, int M, int N, int K,
                          const float* __restrict__ bs, const float* __restrict__ bq,
                          const float* __restrict__ gamma, const float* __restrict__ beta,
                          const float* __restrict__ asrc, const float* __restrict__ adst,
                          float* __restrict__ es, float* __restrict__ ed) {
    __shared__ unsigned As[128][17];
    __shared__ unsigned Bs[16][72];
    __shared__ float sscale[128], sshift[128];
    const int brow = by * 128;
    const int bcol = bx * 64;
    const int tid = threadIdx.x;
    const int w = tid >> 5, l = tid & 31;
    const int wm = w & 3, wn = w >> 2;
    const int mbase = wm * 32, nbase = wn * 32;
    const int g = l >> 2, tg = l & 3;

    if (APPLY_BN) {   // fused BN-finalize: compute per-channel scale/shift from raw sums
        if (tid < K) {
            float m = bs[tid] / (float)NN;
            float var = bq[tid] / (float)NN - m * m;
            float sc = rsqrtf(var + 1e-5f) * gamma[tid];
            sscale[tid] = sc;
            sshift[tid] = beta[tid] - m * sc;
        }
        __syncthreads();
    }

    float4 acc[2][4];
    #pragma unroll
    for (int i = 0; i < 2; i++)
        #pragma unroll
        for (int j = 0; j < 4; j++) acc[i][j] = make_float4(0.f, 0.f, 0.f, 0.f);

    for (int k0 = 0; k0 < K; k0 += 16) {
        #pragma unroll
        for (int i = tid; i < 512; i += 256) {
            int r = i >> 2, c4 = (i & 3) * 4;
            int gr = brow + r;
            float4 v = make_float4(0.f, 0.f, 0.f, 0.f);
            if (gr < M) {
                v = *(const float4*)(A + (long)gr * K + k0 + c4);
                if (APPLY_BN) {
                    int c = k0 + c4;
                    v.x = fmaxf(fmaf(v.x, sscale[c + 0], sshift[c + 0]), 0.f);
                    v.y = fmaxf(fmaf(v.y, sscale[c + 1], sshift[c + 1]), 0.f);
                    v.z = fmaxf(fmaf(v.z, sscale[c + 2], sshift[c + 2]), 0.f);
                    v.w = fmaxf(fmaf(v.w, sscale[c + 3], sshift[c + 3]), 0.f);
                }
            }
            As[r][c4 + 0] = f2tf(v.x);
            As[r][c4 + 1] = f2tf(v.y);
            As[r][c4 + 2] = f2tf(v.z);
            As[r][c4 + 3] = f2tf(v.w);
        }
        {
            int r = tid >> 4, c4 = (tid & 15) * 4;
            float4 v = *(const float4*)(B + (long)(k0 + r) * N + bcol + c4);
            Bs[r][c4 + 0] = f2tf(v.x);
            Bs[r][c4 + 1] = f2tf(v.y);
            Bs[r][c4 + 2] = f2tf(v.z);
            Bs[r][c4 + 3] = f2tf(v.w);
        }
        __syncthreads();
        #pragma unroll
        for (int k8 = 0; k8 < 16; k8 += 8) {
            unsigned af[2][4], bf[4][2];
            #pragma unroll
            for (int mt = 0; mt < 2; mt++) {
                int r0 = mbase + mt * 16 + g;
                int c = k8 + tg;
                af[mt][0] = As[r0][c];
                af[mt][1] = As[r0 + 8][c];
                af[mt][2] = As[r0][c + 4];
                af[mt][3] = As[r0 + 8][c + 4];
            }
            #pragma unroll
            for (int nt = 0; nt < 4; nt++) {
                int cb = nbase + nt * 8 + g;
                int rb = k8 + tg;
                bf[nt][0] = Bs[rb][cb];
                bf[nt][1] = Bs[rb + 4][cb];
            }
            #pragma unroll
            for (int mt = 0; mt < 2; mt++)
                #pragma unroll
                for (int nt = 0; nt < 4; nt++) mma_tf32(acc[mt][nt], af[mt], bf[nt]);
        }
        __syncthreads();
    }

    #pragma unroll
    for (int mt = 0; mt < 2; mt++) {
        #pragma unroll
        for (int nt = 0; nt < 4; nt++) {
            int row = brow + mbase + mt * 16 + g;
            int col = bcol + nbase + nt * 8 + 2 * tg;
            if (row < M)
                *(float2*)(C + (long)row * N + col) = make_float2(acc[mt][nt].x, acc[mt][nt].y);
            if (row + 8 < M)
                *(float2*)(C + (long)(row + 8) * N + col) = make_float2(acc[mt][nt].z, acc[mt][nt].w);
        }
    }

    // fused attention-logit epilogue
    {
        int head = (2 * bcol >= N) ? 1 : 0;
        float av_s[8], av_d[8];
        #pragma unroll
        for (int nt = 0; nt < 4; nt++) {
            int col = bcol + nbase + nt * 8 + 2 * tg;
            av_s[nt * 2 + 0] = __ldg(asrc + col);
            av_s[nt * 2 + 1] = __ldg(asrc + col + 1);
            av_d[nt * 2 + 0] = __ldg(adst + col);
            av_d[nt * 2 + 1] = __ldg(adst + col + 1);
        }
        #pragma unroll
        for (int mt = 0; mt < 2; mt++) {
            float pes0 = 0.f, ped0 = 0.f, pes8 = 0.f, ped8 = 0.f;
            #pragma unroll
            for (int nt = 0; nt < 4; nt++) {
                float4 a = acc[mt][nt];
                pes0 += a.x * av_s[nt * 2] + a.y * av_s[nt * 2 + 1];
                ped0 += a.x * av_d[nt * 2] + a.y * av_d[nt * 2 + 1];
                pes8 += a.z * av_s[nt * 2] + a.w * av_s[nt * 2 + 1];
                ped8 += a.z * av_d[nt * 2] + a.w * av_d[nt * 2 + 1];
            }
            #pragma unroll
            for (int o = 1; o <= 2; o <<= 1) {
                pes0 += __shfl_xor_sync(0xffffffffu, pes0, o);
                ped0 += __shfl_xor_sync(0xffffffffu, ped0, o);
                pes8 += __shfl_xor_sync(0xffffffffu, pes8, o);
                ped8 += __shfl_xor_sync(0xffffffffu, ped8, o);
            }
            if (tg == 0) {
                int row = brow + mbase + mt * 16 + g;
                if (row < M) {
                    atomicAdd(&es[row * 2 + head], pes0);
                    atomicAdd(&ed[row * 2 + head], ped0);
                }
                if (row + 8 < M) {
                    atomicAdd(&es[(row + 8) * 2 + head], pes8);
                    atomicAdd(&ed[(row + 8) * 2 + head], ped8);
                }
            }
        }
    }
}

// ---------------- combo: gemm1 tiles + CSR fill + graph bounds in ONE launch ----------------
__global__ void combo1(const float* __restrict__ x, const float* __restrict__ W1,
                       float* __restrict__ h1,
                       const float* __restrict__ a_s1, const float* __restrict__ a_d1,
                       float* __restrict__ es1, float* __restrict__ ed1,
                       const int* __restrict__ esrc, const int* __restrict__ edst,
                       int* __restrict__ cursor, int* __restrict__ csrc,
                       const int* __restrict__ batch, int* __restrict__ gstart) {
    int bid = blockIdx.x;
    if (bid < GEMM1_BLOCKS) {
        gemm_body<false>(bid & 1, bid >> 1, x, W1, h1, NN, 128, 64,
                         nullptr, nullptr, nullptr, nullptr, a_s1, a_d1, es1, ed1);
    } else if (bid < GEMM1_BLOCKS + CSR_BLOCKS) {
        int idx = (bid - GEMM1_BLOCKS) * 256 + threadIdx.x;
        if (idx < EE) {
            int t = edst[idx];
            int p = atomicAdd(&cursor[t], 1);
            csrc[p] = esrc[idx];
        } else if (idx < EE + NN) {
            int n = idx - EE;
            int p = atomicAdd(&cursor[n], 1);
            csrc[p] = n;
        }
    } else {
        int g = threadIdx.x;
        if (g <= GG) {
            int lo = 0, hi = NN;
            while (lo < hi) {
                int mid = (lo + hi) >> 1;
                if (batch[mid] < g) lo = mid + 1; else hi = mid;
            }
            gstart[g] = lo;
        }
    }
}

__global__ void gemm_k(int nbx, const float* A, const float* B, float* C, int M, int N, int K,
                       const float* bs, const float* bq, const float* gamma, const float* beta,
                       const float* asrc, const float* adst, float* es, float* ed) {
    gemm_body<true>(blockIdx.x % nbx, blockIdx.x / nbx, A, B, C, M, N, K,
                    bs, bq, gamma, beta, asrc, adst, es, ed);
}

// ---------------- fused GAT: softmax (max+exp+denom) + gather + bias + BN stats ----------------
template <int C>
__global__ void fused_gat(const int* __restrict__ off, const int* __restrict__ csrc,
                          const float* __restrict__ es, const float* __restrict__ ed,
                          const float* __restrict__ h, const float* __restrict__ bias,
                          float* __restrict__ y,
                          float* __restrict__ bnsum, float* __restrict__ bnsq) {
    __shared__ float ssum[C];
    __shared__ float ssq[C];
    const int tid = threadIdx.x;
    for (int i = tid; i < C; i += 1024) { ssum[i] = 0.f; ssq[i] = 0.f; }
    __syncthreads();

    int t = blockIdx.x * 32 + (tid >> 5);
    int lane = tid & 31;
    bool valid = t < NN;
    int b = 0, e = 0;
    float ed0 = 0.f, ed1 = 0.f;
    if (valid) {
        b = off[t];
        e = off[t + 1];
        ed0 = ed[t * 2];
        ed1 = ed[t * 2 + 1];
    }

    // pass 1: segment max
    float m0 = -1e30f, m1 = -1e30f;
    for (int i = b + lane; i < e; i += 32) {
        int s = csrc[i];
        float2 esv = *(const float2*)(es + s * 2);
        float v0 = esv.x + ed0; v0 = v0 > 0.f ? v0 : 0.2f * v0;
        float v1 = esv.y + ed1; v1 = v1 > 0.f ? v1 : 0.2f * v1;
        m0 = fmaxf(m0, v0);
        m1 = fmaxf(m1, v1);
    }
    #pragma unroll
    for (int o = 16; o; o >>= 1) {
        m0 = fmaxf(m0, __shfl_xor_sync(0xffffffffu, m0, o));
        m1 = fmaxf(m1, __shfl_xor_sync(0xffffffffu, m1, o));
    }

    // pass 2: exp weights + denom + feature accumulate (unnormalized)
    float den0 = 0.f, den1 = 0.f;
    float4 acc0 = make_float4(0.f, 0.f, 0.f, 0.f);
    float4 acc1 = make_float4(0.f, 0.f, 0.f, 0.f);
    for (int base = b; base < e; base += 32) {
        int n = min(32, e - base);
        float w0 = 0.f, w1 = 0.f;
        int sreg = 0;
        if (lane < n) {
            sreg = csrc[base + lane];
            float2 esv = *(const float2*)(es + sreg * 2);
            float v0 = esv.x + ed0; v0 = v0 > 0.f ? v0 : 0.2f * v0;
            float v1 = esv.y + ed1; v1 = v1 > 0.f ? v1 : 0.2f * v1;
            w0 = __expf(v0 - m0);
            w1 = __expf(v1 - m1);
            den0 += w0;
            den1 += w1;
        }
        for (int j = 0; j < n; j++) {
            int s = __shfl_sync(0xffffffffu, sreg, j);
            float ww0 = __shfl_sync(0xffffffffu, w0, j);
            float ww1 = __shfl_sync(0xffffffffu, w1, j);
            const float* hp = h + (long)s * C;
            if (C == 128) {
                float4 hv = *(const float4*)(hp + lane * 4);
                float w = (lane < 16) ? ww0 : ww1;
                acc0.x += hv.x * w; acc0.y += hv.y * w;
                acc0.z += hv.z * w; acc0.w += hv.w * w;
            } else {
                float4 hv0 = *(const float4*)(hp + lane * 4);
                float4 hv1 = *(const float4*)(hp + 128 + lane * 4);
                acc0.x += hv0.x * ww0; acc0.y += hv0.y * ww0;
                acc0.z += hv0.z * ww0; acc0.w += hv0.w * ww0;
                acc1.x += hv1.x * ww1; acc1.y += hv1.y * ww1;
                acc1.z += hv1.z * ww1; acc1.w += hv1.w * ww1;
            }
        }
    }
    #pragma unroll
    for (int o = 16; o; o >>= 1) {
        den0 += __shfl_xor_sync(0xffffffffu, den0, o);
        den1 += __shfl_xor_sync(0xffffffffu, den1, o);
    }

    if (valid) {
        float r0 = 1.f / (den0 + 1e-16f);
        float r1 = 1.f / (den1 + 1e-16f);
        if (C == 128) {
            float r = (lane < 16) ? r0 : r1;
            int c = lane * 4;
            const float4 bb = *(const float4*)(bias + c);
            float4 o = make_float4(acc0.x * r + bb.x, acc0.y * r + bb.y,
                                   acc0.z * r + bb.z, acc0.w * r + bb.w);
            *(float4*)(y + (long)t * C + c) = o;
            atomicAdd(&ssum[c + 0], o.x); atomicAdd(&ssq[c + 0], o.x * o.x);
            atomicAdd(&ssum[c + 1], o.y); atomicAdd(&ssq[c + 1], o.y * o.y);
            atomicAdd(&ssum[c + 2], o.z); atomicAdd(&ssq[c + 2], o.z * o.z);
            atomicAdd(&ssum[c + 3], o.w); atomicAdd(&ssq[c + 3], o.w * o.w);
        } else {
            int c0 = lane * 4, c1 = 128 + lane * 4;
            const float4 b0 = *(const float4*)(bias + c0);
            const float4 b1 = *(const float4*)(bias + c1);
            float4 o0 = make_float4(acc0.x * r0 + b0.x, acc0.y * r0 + b0.y,
                                    acc0.z * r0 + b0.z, acc0.w * r0 + b0.w);
            float4 o1 = make_float4(acc1.x * r1 + b1.x, acc1.y * r1 + b1.y,
                                    acc1.z * r1 + b1.z, acc1.w * r1 + b1.w);
            *(float4*)(y + (long)t * C + c0) = o0;
            *(float4*)(y + (long)t * C + c1) = o1;
            atomicAdd(&ssum[c0 + 0], o0.x); atomicAdd(&ssq[c0 + 0], o0.x * o0.x);
            atomicAdd(&ssum[c0 + 1], o0.y); atomicAdd(&ssq[c0 + 1], o0.y * o0.y);
            atomicAdd(&ssum[c0 + 2], o0.z); atomicAdd(&ssq[c0 + 2], o0.z * o0.z);
            atomicAdd(&ssum[c0 + 3], o0.w); atomicAdd(&ssq[c0 + 3], o0.w * o0.w);
            atomicAdd(&ssum[c1 + 0], o1.x); atomicAdd(&ssq[c1 + 0], o1.x * o1.x);
            atomicAdd(&ssum[c1 + 1], o1.y); atomicAdd(&ssq[c1 + 1], o1.y * o1.y);
            atomicAdd(&ssum[c1 + 2], o1.z); atomicAdd(&ssq[c1 + 2], o1.z * o1.z);
            atomicAdd(&ssum[c1 + 3], o1.w); atomicAdd(&ssq[c1 + 3], o1.w * o1.w);
        }
    }
    __syncthreads();
    for (int i = tid; i < C; i += 1024) {
        atomicAdd(&bnsum[i], ssum[i]);
        atomicAdd(&bnsq[i], ssq[i]);
    }
}

// ---------------- pooling: one block per graph; fused BN2-finalize + relu; no atomics ----------------
__global__ void pool_bn(const float* __restrict__ y2, const int* __restrict__ gstart,
                        const float* __restrict__ bs, const float* __restrict__ bq,
                        const float* __restrict__ gamma, const float* __restrict__ beta,
                        float* __restrict__ pooled) {
    int c = threadIdx.x;  // 256
    float m = bs[c] / (float)NN;
    float var = bq[c] / (float)NN - m * m;
    float sc = rsqrtf(var + 1e-5f) * gamma[c];
    float sh = beta[c] - m * sc;
    int g = blockIdx.x;
    int b = gstart[g], e = gstart[g + 1];
    float s = 0.f;
    for (int r = b; r < e; r++) s += fmaxf(fmaf(y2[(long)r * 256 + c], sc, sh), 0.f);
    pooled[g * 256 + c] = s / fmaxf((float)(e - b), 1.f);
}

// ---------------- FC head ----------------
__global__ void fc_kernel(const float* __restrict__ in, const float* __restrict__ W,
                          const float* __restrict__ b, float* __restrict__ out,
                          int M, int N, int K) {
    int idx = blockIdx.x * blockDim.x + threadIdx.x;
    if (idx >= M * N) return;
    int r = idx / N, c = idx % N;
    float s = b[c];
    for (int k = 0; k < K; k++) s += in[r * K + k] * W[k * N + c];
    out[idx] = s;
}

__global__ void bn_small_relu(const float* __restrict__ in, const float* __restrict__ g,
                              const float* __restrict__ b, float* __restrict__ out, int C) {
    int c = blockIdx.x * blockDim.x + threadIdx.x;
    if (c >= C) return;
    float s = 0.f, sq = 0.f;
    for (int r = 0; r < GG; r++) {
        float v = in[r * C + c];
        s += v;
        sq += v * v;
    }
    float mu = s / (float)GG;
    float rstd = rsqrtf(sq / (float)GG - mu * mu + 1e-5f);
    for (int r = 0; r < GG; r++) {
        float v = (in[r * C + c] - mu) * rstd * g[c] + b[c];
        out[r * C + c] = fmaxf(v, 0.f);
    }
}

// BN over z2 + final linear, single block
__global__ void bn2_final(const float* __restrict__ z2, const float* __restrict__ g2,
                          const float* __restrict__ b2, const float* __restrict__ Wout,
                          const float* __restrict__ bout, float* __restrict__ z2n,
                          float* __restrict__ out) {
    int c = threadIdx.x;  // 256
    float s = 0.f, sq = 0.f;
    for (int r = 0; r < GG; r++) {
        float v = z2[r * 256 + c];
        s += v;
        sq += v * v;
    }
    float mu = s / (float)GG;
    float rstd = rsqrtf(sq / (float)GG - mu * mu + 1e-5f);
    for (int r = 0; r < GG; r++) {
        float v = (z2[r * 256 + c] - mu) * rstd * g2[c] + b2[c];
        z2n[r * 256 + c] = fmaxf(v, 0.f);
    }
    __syncthreads();
    if (c < GG) {
        float acc = bout[0];
        for (int k = 0; k < 256; k++) acc += z2n[c * 256 + k] * Wout[k];
        out[c] = acc;
    }
}

// ---------------- tail cleanup: re-zero accumulators for the next graph replay ----------------
__global__ void cleanup(int* __restrict__ deg, float* __restrict__ es1, float* __restrict__ ed1,
                        float* __restrict__ es2, float* __restrict__ ed2,
                        float* __restrict__ bs1, float* __restrict__ bq1,
                        float* __restrict__ bs2, float* __restrict__ bq2) {
    int i = blockIdx.x * blockDim.x + threadIdx.x;
    if (i < NN) deg[i] = 0;
    if (i < NN * 2) { es1[i] = 0.f; ed1[i] = 0.f; es2[i] = 0.f; ed2[i] = 0.f; }
    if (i < 128) { bs1[i] = 0.f; bq1[i] = 0.f; }
    if (i < 256) { bs2[i] = 0.f; bq2[i] = 0.f; }
}

// ---------------- host driver ----------------
static inline int cdiv(long a, int b) { return (int)((a + b - 1) / b); }

extern "C" void kernel_launch(void* const* d_in, const int* in_sizes, int n_in,
                              void* d_out, int out_size) {
    const float* x    = (const float*)d_in[0];
    const int*   esrc = (const int*)d_in[1];
    const int*   edst = (const int*)d_in[2];
    const int*   batch= (const int*)d_in[3];
    const float* W1   = (const float*)d_in[4];
    const float* a_s1 = (const float*)d_in[5];
    const float* a_d1 = (const float*)d_in[6];
    const float* b1   = (const float*)d_in[7];
    const float* g1   = (const float*)d_in[8];
    const float* be1  = (const float*)d_in[9];
    const float* W2   = (const float*)d_in[10];
    const float* a_s2 = (const float*)d_in[11];
    const float* a_d2 = (const float*)d_in[12];
    const float* b2   = (const float*)d_in[13];
    const float* g2   = (const float*)d_in[14];
    const float* be2  = (const float*)d_in[15];
    const float* Wf1  = (const float*)d_in[16];
    const float* bf1  = (const float*)d_in[17];
    const float* gf1  = (const float*)d_in[18];
    const float* bef1 = (const float*)d_in[19];
    const float* Wf2  = (const float*)d_in[20];
    const float* bf2  = (const float*)d_in[21];
    const float* gf2  = (const float*)d_in[22];
    const float* bef2 = (const float*)d_in[23];
    const float* Wout = (const float*)d_in[24];
    const float* bout = (const float*)d_in[25];
    float* out = (float*)d_out;

    float *h1, *y1, *h2, *y2, *es1, *ed1, *es2, *ed2;
    int *deg, *off, *cursor, *csrc, *gstart;
    float *bs1, *bq1, *bs2, *bq2, *pooled, *z1, *z1n, *z2, *z2n;
    cudaGetSymbolAddress((void**)&h1, d_h1);
    cudaGetSymbolAddress((void**)&y1, d_y1);
    cudaGetSymbolAddress((void**)&h2, d_h2);
    cudaGetSymbolAddress((void**)&y2, d_y2);
    cudaGetSymbolAddress((void**)&es1, d_es1);
    cudaGetSymbolAddress((void**)&ed1, d_ed1);
    cudaGetSymbolAddress((void**)&es2, d_es2);
    cudaGetSymbolAddress((void**)&ed2, d_ed2);
    cudaGetSymbolAddress((void**)&deg, d_deg);
    cudaGetSymbolAddress((void**)&off, d_off);
    cudaGetSymbolAddress((void**)&cursor, d_cursor);
    cudaGetSymbolAddress((void**)&csrc, d_csrc);
    cudaGetSymbolAddress((void**)&gstart, d_gstart);
    cudaGetSymbolAddress((void**)&bs1, d_bs1);
    cudaGetSymbolAddress((void**)&bq1, d_bq1);
    cudaGetSymbolAddress((void**)&bs2, d_bs2);
    cudaGetSymbolAddress((void**)&bq2, d_bq2);
    cudaGetSymbolAddress((void**)&pooled, d_pooled);
    cudaGetSymbolAddress((void**)&z1, d_z1);
    cudaGetSymbolAddress((void**)&z1n, d_z1n);
    cudaGetSymbolAddress((void**)&z2, d_z2);
    cudaGetSymbolAddress((void**)&z2n, d_z2n);

    const int TB = 256;

    // 1: degree count (deg zeroed by initial load / tail cleanup)
    count_deg<<<cdiv(EE, TB), TB>>>(edst, deg);
    // 2: offsets scan (+1 self-loop folded in)
    scan_offsets<<<1, 1024>>>(deg, off, cursor);
    // 3: gemm1 + CSR fill + graph bounds, one launch
    combo1<<<GEMM1_BLOCKS + CSR_BLOCKS + 1, 256>>>(x, W1, h1, a_s1, a_d1, es1, ed1,
                                                   esrc, edst, cursor, csrc, batch, gstart);
    // 4: fused GAT layer 1  (ncu window)
    fused_gat<128><<<cdiv(NN, 32), 1024>>>(off, csrc, es1, ed1, h1, b1, y1, bs1, bq1);
    // 5: gemm2 (BN1 finalize+apply fused) + attn epilogue
    gemm_k<<<4 * cdiv(NN, 128), 256>>>(4, y1, W2, h2, NN, 256, 128,
                                       bs1, bq1, g1, be1, a_s2, a_d2, es2, ed2);
    // 6: fused GAT layer 2
    fused_gat<256><<<cdiv(NN, 32), 1024>>>(off, csrc, es2, ed2, h2, b2, y2, bs2, bq2);
    // 7: pool (BN2 finalize+relu fused, no atomics)
    pool_bn<<<GG, 256>>>(y2, gstart, bs2, bq2, g2, be2, pooled);
    // 8-11: FC head
    fc_kernel<<<cdiv(GG * 512, TB), TB>>>(pooled, Wf1, bf1, z1, GG, 512, 256);
    bn_small_relu<<<2, 256>>>(z1, gf1, bef1, z1n, 512);
    fc_kernel<<<cdiv(GG * 256, TB), TB>>>(z1n, Wf2, bf2, z2, GG, 256, 512);
    bn2_final<<<1, 256>>>(z2, gf2, bef2, Wout, bout, z2n, out);
    // 12: tail cleanup for next replay
    cleanup<<<cdiv(NN * 2, TB), TB>>>(deg, es1, ed1, es2, ed2, bs1, bq1, bs2, bq2);
}